// round 11
// baseline (speedup 1.0000x reference)
#include <cuda_runtime.h>
#include <cuda_bf16.h>
#include <math.h>
#include <stdint.h>

// ---------------- problem constants ----------------
constexpr int N_ATOMS = 10000;
constexpr int N_EDGES = 64000;
constexpr int N_BATCH = 128;
constexpr int H = 600;
constexpr int H4 = H / 4;
constexpr int G = 50;
constexpr int L = 6;
constexpr float CUTOFF = 10.0f;
constexpr float LN2 = 0.69314718055994530942f;

constexpr int KP  = 1824;   // padded 3*H (multiple of 32)
constexpr int KPG = 160;    // padded 3*G (multiple of 32)
constexpr int S_TAB = 1024; // distance table rows
constexpr float DMAX = 8.66035f;

// ---------------- scratch (device globals, zero-initialized) ----------------
__device__ __nv_bfloat16 g_rbf_s[(size_t)S_TAB * KPG];
__device__ float         g_Ct[S_TAB];
__device__ int           g_ei0[N_EDGES];
__device__ float         g_ef[N_EDGES];
__device__ float         g_h[N_ATOMS * H];
__device__ __nv_bfloat16 g_hs[(size_t)N_ATOMS * KP];
__device__ __nv_bfloat16 g_T1s[2 * (size_t)S_TAB * KP];   // ping-pong T1 table
__device__ float         g_Wtab[(size_t)S_TAB * H];
__device__ float         g_Y[N_ATOMS * H];
__device__ float         g_agg[N_ATOMS * H];
__device__ __nv_bfloat16 g_aggs[(size_t)N_ATOMS * KP];
__device__ __nv_bfloat16 g_x1s[(size_t)N_ATOMS * KP];
__device__ float         g_pooled[N_BATCH * H];
__device__ __nv_bfloat16 g_pooled_s[(size_t)N_BATCH * KP];
__device__ float         g_cnt[N_BATCH];
// split weights for ALL layers (written once per launch, before the loop)
__device__ __nv_bfloat16 g_w1s[(size_t)L * KPG * H];
__device__ __nv_bfloat16 g_w2s[(size_t)L * KP * H];
__device__ __nv_bfloat16 g_l1ws[(size_t)L * KP * H];
__device__ __nv_bfloat16 g_l2ws[(size_t)L * KP * H];
__device__ __nv_bfloat16 g_ilws[(size_t)L * KP * H];
__device__ __nv_bfloat16 g_pws[(size_t)KP * H];

// ---------------- compile-time buffer picker ----------------
enum BufId { B_NONE = -1,
             B_RBFS = 0, B_T1S, B_HS, B_AGGS, B_X1S, B_POOLS,
             B_W1S, B_W2S, B_L1WS, B_L2WS, B_ILWS, B_PWS,
             B_WTAB, B_Y, B_H, B_AGG, B_POOLED, B_PARAM };

template <int B>
__device__ __forceinline__ __nv_bfloat16* bbuf() {
    if constexpr (B == B_RBFS)       return g_rbf_s;
    else if constexpr (B == B_T1S)   return g_T1s;
    else if constexpr (B == B_HS)    return g_hs;
    else if constexpr (B == B_AGGS)  return g_aggs;
    else if constexpr (B == B_X1S)   return g_x1s;
    else if constexpr (B == B_POOLS) return g_pooled_s;
    else if constexpr (B == B_W1S)   return g_w1s;
    else if constexpr (B == B_W2S)   return g_w2s;
    else if constexpr (B == B_L1WS)  return g_l1ws;
    else if constexpr (B == B_L2WS)  return g_l2ws;
    else if constexpr (B == B_ILWS)  return g_ilws;
    else return g_pws;
}
template <int B>
__device__ __forceinline__ float* fbuf(float* p) {
    if constexpr (B == B_WTAB)        return g_Wtab;
    else if constexpr (B == B_Y)      return g_Y;
    else if constexpr (B == B_H)      return g_h;
    else if constexpr (B == B_AGG)    return g_agg;
    else if constexpr (B == B_POOLED) return g_pooled;
    else return p;
}

// ---------------- helpers ----------------
__device__ __forceinline__ float sspf(float x) {
    return fmaxf(x, 0.0f) + log1pf(expf(-fabsf(x))) - LN2;
}
__device__ __forceinline__ void split2(float v, __nv_bfloat16& hi, __nv_bfloat16& lo) {
    hi = __float2bfloat16(v);
    lo = __float2bfloat16(v - __bfloat162float(hi));
}
// split 4 values; write hi x4 / lo x4 / hi x4 (8B each) into split layout
__device__ __forceinline__ void split_store4(__nv_bfloat16* dst, size_t base,
                                             int k, float4 v) {
    __nv_bfloat16 h0, l0, h1, l1, h2, l2, h3, l3;
    split2(v.x, h0, l0); split2(v.y, h1, l1);
    split2(v.z, h2, l2); split2(v.w, h3, l3);
    __nv_bfloat162 hp0 = {h0, h1}, hp1 = {h2, h3};
    __nv_bfloat162 lp0 = {l0, l1}, lp1 = {l2, l3};
    *(uint2*)(dst + base + k) =
        make_uint2(*(uint32_t*)&hp0, *(uint32_t*)&hp1);
    *(uint2*)(dst + base + H + k) =
        make_uint2(*(uint32_t*)&lp0, *(uint32_t*)&lp1);
    *(uint2*)(dst + base + 2 * H + k) =
        make_uint2(*(uint32_t*)&hp0, *(uint32_t*)&hp1);
}

// ---------------- edge geometry ----------------
__global__ void edge_geom_kernel(const float* __restrict__ pos,
                                 const int* __restrict__ ei) {
    int e = blockIdx.x * blockDim.x + threadIdx.x;
    if (e >= N_EDGES) return;
    int s = ei[e];
    int d = ei[N_EDGES + e];
    float dx = pos[s * 3 + 0] - pos[d * 3 + 0];
    float dy = pos[s * 3 + 1] - pos[d * 3 + 1];
    float dz = pos[s * 3 + 2] - pos[d * 3 + 2];
    float dist = sqrtf(dx * dx + dy * dy + dz * dz + 1e-12f);
    float x = dist * ((float)(S_TAB - 1) / DMAX);
    int i0 = (int)x;
    if (i0 > S_TAB - 2) i0 = S_TAB - 2;
    g_ei0[e] = i0;
    g_ef[e] = x - (float)i0;
}

// ---------------- rbf table ----------------
__global__ void rbf_table_kernel() {
    int i = blockIdx.x * blockDim.x + threadIdx.x;
    if (i >= S_TAB) return;
    float dist = (float)i * (DMAX / (float)(S_TAB - 1));
    g_Ct[i] = 0.5f * (cosf(dist * (3.14159265358979323846f / CUTOFF)) + 1.0f);
    const float step = CUTOFF / (float)(G - 1);
    const float coeff = -0.5f / (step * step);
    size_t base = (size_t)i * KPG;
    #pragma unroll
    for (int g = 0; g < G; g++) {
        float t = dist - step * (float)g;
        float v = expf(coeff * t * t);
        __nv_bfloat16 hi, lo; split2(v, hi, lo);
        g_rbf_s[base + g]         = hi;
        g_rbf_s[base + G + g]     = lo;
        g_rbf_s[base + 2 * G + g] = hi;
    }
}

// ---------------- embedding gather (vectorized) ----------------
__global__ void embed_kernel(const int* __restrict__ z,
                             const float* __restrict__ emb) {
    int idx = blockIdx.x * blockDim.x + threadIdx.x;
    const int total = N_ATOMS * H4;
    if (idx >= total) return;
    int i = idx / H4;
    int c4 = idx - i * H4;
    int k = c4 * 4;
    float4 v = *(const float4*)(emb + (size_t)__ldg(&z[i]) * H + k);
    *(float4*)(g_h + (size_t)i * H + k) = v;
    split_store4(g_hs, (size_t)i * KP, k, v);
}

// ---------------- split ALL H x H layer weights ----------------
__global__ void split_w_all_kernel(const float* __restrict__ w2,
                                   const float* __restrict__ l1w,
                                   const float* __restrict__ l2w,
                                   const float* __restrict__ ilw) {
    long long idx = (long long)blockIdx.x * blockDim.x + threadIdx.x;
    const int per = H * H;
    const long long total = (long long)L * 4 * per;
    if (idx >= total) return;
    int t = (int)(idx / per);
    int j = (int)(idx - (long long)t * per);
    int layer = t >> 2, which = t & 3;
    const float* src = ((which == 0) ? w2 : (which == 1) ? l1w
                      : (which == 2) ? l2w : ilw) + (size_t)layer * per;
    __nv_bfloat16* dst = ((which == 0) ? g_w2s : (which == 1) ? g_l1ws
                        : (which == 2) ? g_l2ws : g_ilws) + (size_t)layer * KP * H;
    int r = j / H, n = j - r * H;
    __nv_bfloat16 hi, lo; split2(src[j], hi, lo);
    dst[(size_t)r * H + n]           = hi;
    dst[(size_t)(H + r) * H + n]     = hi;
    dst[(size_t)(2 * H + r) * H + n] = lo;
}

__global__ void split_w1_pool_kernel(const float* __restrict__ w1,
                                     const float* __restrict__ pw) {
    int idx = blockIdx.x * blockDim.x + threadIdx.x;
    const int tot1 = L * G * H;
    if (idx < tot1) {
        int layer = idx / (G * H);
        int j = idx - layer * (G * H);
        int r = j / H, n = j - r * H;
        __nv_bfloat16 hi, lo; split2(w1[idx], hi, lo);
        __nv_bfloat16* dst = g_w1s + (size_t)layer * KPG * H;
        dst[(size_t)r * H + n]           = hi;
        dst[(size_t)(G + r) * H + n]     = hi;
        dst[(size_t)(2 * G + r) * H + n] = lo;
    }
    int idx2 = idx - tot1;
    if (idx2 >= 0 && idx2 < H * H) {
        int r = idx2 / H, n = idx2 - r * H;
        __nv_bfloat16 hi, lo; split2(pw[idx2], hi, lo);
        g_pws[(size_t)r * H + n]           = hi;
        g_pws[(size_t)(H + r) * H + n]     = hi;
        g_pws[(size_t)(2 * H + r) * H + n] = lo;
    }
}

// ---------------- activation split (vectorized) ----------------
template <int SRCF, int DSTB>
__global__ void split_act_kernel(int M) {
    const float* src = fbuf<SRCF>(nullptr);
    __nv_bfloat16* dst = bbuf<DSTB>();
    int idx = blockIdx.x * blockDim.x + threadIdx.x;
    int total = M * H4;
    if (idx >= total) return;
    int m = idx / H4;
    int c4 = idx - m * H4;
    int k = c4 * 4;
    float4 v = *(const float4*)(src + (size_t)m * H + k);
    split_store4(dst, (size_t)m * KP, k, v);
}

// ---------------- pooling small kernels ----------------
__global__ void zero_pool_kernel() {
    int idx = blockIdx.x * blockDim.x + threadIdx.x;
    if (idx < N_BATCH * H4)
        ((float4*)g_pooled)[idx] = make_float4(0.f, 0.f, 0.f, 0.f);
    if (idx < N_BATCH) g_cnt[idx] = 0.0f;
}
// pool_sum with integrated count
__global__ void pool_sum_kernel(const int* __restrict__ batch) {
    int idx = blockIdx.x * blockDim.x + threadIdx.x;
    const int total = N_ATOMS * H4;
    if (idx >= total) return;
    int i = idx / H4;
    int c4 = idx - i * H4;
    int b = __ldg(&batch[i]);
    if (c4 == 0) atomicAdd(&g_cnt[b], 1.0f);
    const float4 v = *(const float4*)(g_h + (size_t)i * H + c4 * 4);
    float* dst = g_pooled + (size_t)b * H + c4 * 4;
    asm volatile("red.global.v4.f32.add [%0], {%1,%2,%3,%4};"
                 :: "l"(dst), "f"(v.x), "f"(v.y), "f"(v.z), "f"(v.w) : "memory");
}
// divide by count AND write split in one pass
__global__ void pool_divsplit_kernel() {
    int idx = blockIdx.x * blockDim.x + threadIdx.x;
    if (idx >= N_BATCH * H) return;
    int b = idx / H, c = idx - b * H;
    float v = g_pooled[idx] / fmaxf(g_cnt[b], 1.0f);
    __nv_bfloat16 hi, lo; split2(v, hi, lo);
    size_t base = (size_t)b * KP;
    g_pooled_s[base + c]         = hi;
    g_pooled_s[base + H + c]     = lo;
    g_pooled_s[base + 2 * H + c] = hi;
}

// ---------------- HMMA GEMM body (4-stage cp.async pipeline) ----------------
constexpr int GBM = 128, GBN = 128, GBK = 32;
constexpr int APAD = 8, BPAD = 8;
constexpr int AST = GBK + APAD;
constexpr int BST = GBN + BPAD;
constexpr uint32_t A_BYTES = GBM * AST * 2;
constexpr uint32_t B_BYTES = GBK * BST * 2;
constexpr uint32_t STG_BYTES = A_BYTES + B_BYTES;
constexpr int NSTAGE = 4;
constexpr uint32_t SMEM_SZ = NSTAGE * STG_BYTES;        // 75776

#define MMA16816(ac, A0, A1, A2, A3, B0, B1)                              \
    asm volatile(                                                         \
        "mma.sync.aligned.m16n8k16.row.col.f32.bf16.bf16.f32 "            \
        "{%0,%1,%2,%3},{%4,%5,%6,%7},{%8,%9},{%0,%1,%2,%3};\n"            \
        : "+f"(ac[0]), "+f"(ac[1]), "+f"(ac[2]), "+f"(ac[3])              \
        : "r"(A0), "r"(A1), "r"(A2), "r"(A3), "r"(B0), "r"(B1))

// EPI: 0 = +bias, 1 = ssp(+bias), 2 = (+bias)*g_Ct[m], 3 = +bias + g_h[m,n]
// ZAGG: epilogue also zeroes g_agg[gm,gn]
template <int ABUF, int BBUF, int CF32, int CSPL, int EPI, bool ZAGG,
          int M_, int KPA_>
__device__ __forceinline__
void gemm_body(const float* __restrict__ bias, float* out_param,
               size_t aoff, size_t boff, size_t csoff, int by) {
    const __nv_bfloat16* __restrict__ A  = bbuf<ABUF>() + aoff;
    const __nv_bfloat16* __restrict__ Bw = bbuf<BBUF>() + boff;
    float* Cf = nullptr;
    if constexpr (CF32 != B_NONE) Cf = fbuf<CF32>(out_param);
    __nv_bfloat16* Cs = nullptr;
    if constexpr (CSPL != B_NONE) Cs = bbuf<CSPL>() + csoff;

    extern __shared__ char dsm[];
    uint32_t sb;
    asm("{ .reg .u64 t; cvta.to.shared.u64 t, %1; cvt.u32.u64 %0, t; }"
        : "=r"(sb) : "l"(dsm));

    const int tid = threadIdx.x;
    const int lane = tid & 31, wid = tid >> 5;
    const int wm = (wid >> 1) * 32;
    const int wn = (wid & 1) * 64;
    const int bm = by * GBM, bn = blockIdx.x * GBN;

    float acc[2][8][4];
    #pragma unroll
    for (int mi = 0; mi < 2; mi++)
        #pragma unroll
        for (int ni = 0; ni < 8; ni++)
            #pragma unroll
            for (int c = 0; c < 4; c++) acc[mi][ni][c] = 0.0f;

    constexpr int KT = KPA_ / GBK;

    auto load_tiles = [&](int kt, int st) {
        int k0 = kt * GBK;
        uint32_t abase = sb + st * STG_BYTES;
        uint32_t bbase = abase + A_BYTES;
        #pragma unroll
        for (int c0 = 0; c0 < 2; c0++) {
            int c = tid + c0 * 256;
            int m = c >> 2, kc = (c & 3) * 8;
            const __nv_bfloat16* src = A + (size_t)(bm + m) * KPA_ + k0 + kc;
            uint32_t dst = abase + (m * AST + kc) * 2;
            int sz = (bm + m < M_) ? 16 : 0;
            asm volatile("cp.async.cg.shared.global [%0],[%1],16,%2;\n"
                         :: "r"(dst), "l"(src), "r"(sz));
        }
        #pragma unroll
        for (int c0 = 0; c0 < 2; c0++) {
            int c = tid + c0 * 256;
            int k = c >> 4, nc = (c & 15) * 8;
            const __nv_bfloat16* src = Bw + (size_t)(k0 + k) * H + bn + nc;
            uint32_t dst = bbase + (k * BST + nc) * 2;
            int sz = (bn + nc < H) ? 16 : 0;
            asm volatile("cp.async.cg.shared.global [%0],[%1],16,%2;\n"
                         :: "r"(dst), "l"(src), "r"(sz));
        }
        asm volatile("cp.async.commit_group;\n");
    };

    constexpr int npre = (KT < NSTAGE) ? KT : NSTAGE;
    #pragma unroll
    for (int s = 0; s < npre; s++) load_tiles(s, s);

    #pragma unroll 1
    for (int kt = 0; kt < KT; kt++) {
        int remaining = KT - 1 - kt;
        if (remaining >= 3)      asm volatile("cp.async.wait_group 3;\n");
        else if (remaining == 2) asm volatile("cp.async.wait_group 2;\n");
        else if (remaining == 1) asm volatile("cp.async.wait_group 1;\n");
        else                     asm volatile("cp.async.wait_group 0;\n");
        __syncthreads();

        int st = kt % NSTAGE;
        uint32_t abase = sb + st * STG_BYTES;
        uint32_t bbase = abase + A_BYTES;

        #pragma unroll
        for (int ks = 0; ks < 2; ks++) {
            const int kk = ks * 16;
            uint32_t a[2][4], b[4][4];
            #pragma unroll
            for (int mi = 0; mi < 2; mi++) {
                int row = wm + mi * 16 + (lane & 15);
                int col = kk + (lane >> 4) * 8;
                uint32_t addr = abase + (row * AST + col) * 2;
                asm volatile("ldmatrix.sync.aligned.m8n8.x4.shared.b16 {%0,%1,%2,%3},[%4];\n"
                             : "=r"(a[mi][0]), "=r"(a[mi][1]), "=r"(a[mi][2]), "=r"(a[mi][3])
                             : "r"(addr));
            }
            #pragma unroll
            for (int ng = 0; ng < 4; ng++) {
                int row = kk + (lane & 15);
                int col = wn + ng * 16 + (lane >> 4) * 8;
                uint32_t addr = bbase + (row * BST + col) * 2;
                asm volatile("ldmatrix.sync.aligned.m8n8.x4.trans.shared.b16 {%0,%1,%2,%3},[%4];\n"
                             : "=r"(b[ng][0]), "=r"(b[ng][1]), "=r"(b[ng][2]), "=r"(b[ng][3])
                             : "r"(addr));
            }
            #pragma unroll
            for (int mi = 0; mi < 2; mi++)
                #pragma unroll
                for (int ni = 0; ni < 8; ni++) {
                    uint32_t b0 = b[ni >> 1][(ni & 1) * 2 + 0];
                    uint32_t b1 = b[ni >> 1][(ni & 1) * 2 + 1];
                    MMA16816(acc[mi][ni], a[mi][0], a[mi][1], a[mi][2], a[mi][3], b0, b1);
                }
        }
        __syncthreads();
        if (kt + NSTAGE < KT) load_tiles(kt + NSTAGE, st);
    }

    #pragma unroll
    for (int mi = 0; mi < 2; mi++) {
        #pragma unroll
        for (int r = 0; r < 2; r++) {
            int gm = bm + wm + mi * 16 + (lane >> 2) + r * 8;
            if (gm >= M_) continue;
            float cs = 0.0f;
            if constexpr (EPI == 2) cs = g_Ct[gm];
            #pragma unroll
            for (int ni = 0; ni < 8; ni++) {
                #pragma unroll
                for (int cc = 0; cc < 2; cc++) {
                    int gn = bn + wn + ni * 8 + (lane & 3) * 2 + cc;
                    if (gn >= H) continue;
                    float v = acc[mi][ni][r * 2 + cc];
                    if (bias) v += bias[gn];
                    if constexpr (EPI == 1) v = sspf(v);
                    if constexpr (EPI == 2) v *= cs;
                    if constexpr (EPI == 3) v += g_h[(size_t)gm * H + gn];
                    if constexpr (CF32 != B_NONE) Cf[(size_t)gm * H + gn] = v;
                    if constexpr (ZAGG) g_agg[(size_t)gm * H + gn] = 0.0f;
                    if constexpr (CSPL != B_NONE) {
                        __nv_bfloat16 hi, lo; split2(v, hi, lo);
                        size_t base = (size_t)gm * KP;
                        Cs[base + gn]         = hi;
                        Cs[base + H + gn]     = lo;
                        Cs[base + 2 * H + gn] = hi;
                    }
                }
            }
        }
    }
}

// single-problem GEMM
template <int ABUF, int BBUF, int CF32, int CSPL, int EPI, bool ZAGG,
          int M_, int KPA_>
__global__ __launch_bounds__(256, 2)
void hgemm_kernel(const float* __restrict__ bias, float* out_param,
                  size_t aoff, size_t boff, size_t csoff) {
    gemm_body<ABUF, BBUF, CF32, CSPL, EPI, ZAGG, M_, KPA_>(
        bias, out_param, aoff, boff, csoff, blockIdx.y);
}

// fused launch: [ Y(k) + zero_agg | Wtab(k) | T1tab(k+1) ]
constexpr int NBY_Y = (N_ATOMS + GBM - 1) / GBM;   // 79
constexpr int NBY_T = S_TAB / GBM;                 // 8
__global__ __launch_bounds__(256, 2)
void hgemm_fused3(const float* __restrict__ b2, const float* __restrict__ b1n,
                  size_t offL1, size_t offW2, size_t offW1n,
                  size_t t1rd, size_t t1wr) {
    int by = blockIdx.y;
    if (by < NBY_Y) {
        gemm_body<B_HS, B_L1WS, B_Y, B_NONE, 0, true, N_ATOMS, KP>(
            nullptr, nullptr, 0, offL1, 0, by);
    } else if (by < NBY_Y + NBY_T) {
        gemm_body<B_T1S, B_W2S, B_WTAB, B_NONE, 2, false, S_TAB, KP>(
            b2, nullptr, t1rd, offW2, 0, by - NBY_Y);
    } else {
        gemm_body<B_RBFS, B_W1S, B_NONE, B_T1S, 1, false, S_TAB, KPG>(
            b1n, nullptr, 0, offW1n, t1wr, by - NBY_Y - NBY_T);
    }
}

// ---------------- CFConv scatter: vectorized lerp + red.v4 ----------------
__global__ void scatter_kernel(const int* __restrict__ ei) {
    int idx = blockIdx.x * blockDim.x + threadIdx.x;
    const int total = N_EDGES * H4;
    if (idx >= total) return;
    int e = idx / H4;
    int c4 = idx - e * H4;
    int s  = __ldg(&ei[e]);
    int d  = __ldg(&ei[N_EDGES + e]);
    int i0 = __ldg(&g_ei0[e]);
    float f = __ldg(&g_ef[e]);
    const float4 y  = *(const float4*)(g_Y    + (size_t)s * H        + c4 * 4);
    const float4 w0 = *(const float4*)(g_Wtab + (size_t)i0 * H       + c4 * 4);
    const float4 w1 = *(const float4*)(g_Wtab + (size_t)(i0 + 1) * H + c4 * 4);
    float v0 = y.x * fmaf(f, w1.x - w0.x, w0.x);
    float v1 = y.y * fmaf(f, w1.y - w0.y, w0.y);
    float v2 = y.z * fmaf(f, w1.z - w0.z, w0.z);
    float v3 = y.w * fmaf(f, w1.w - w0.w, w0.w);
    float* dst = g_agg + (size_t)d * H + c4 * 4;
    asm volatile("red.global.v4.f32.add [%0], {%1,%2,%3,%4};"
                 :: "l"(dst), "f"(v0), "f"(v1), "f"(v2), "f"(v3) : "memory");
}

// ---------------- host side ----------------
extern "C" void kernel_launch(void* const* d_in, const int* in_sizes, int n_in,
                              void* d_out, int out_size) {
    const int*   z         = (const int*)  d_in[0];
    const float* pos       = (const float*)d_in[1];
    const int*   batch     = (const int*)  d_in[2];
    const int*   ei        = (const int*)  d_in[3];
    const float* emb       = (const float*)d_in[4];
    const float* mlp_w1    = (const float*)d_in[5];
    const float* mlp_b1    = (const float*)d_in[6];
    const float* mlp_w2    = (const float*)d_in[7];
    const float* mlp_b2    = (const float*)d_in[8];
    const float* lin1_w    = (const float*)d_in[9];
    const float* lin2_w    = (const float*)d_in[10];
    const float* lin2_b    = (const float*)d_in[11];
    const float* int_lin_w = (const float*)d_in[12];
    const float* int_lin_b = (const float*)d_in[13];
    const float* pool_w    = (const float*)d_in[14];
    const float* pool_b    = (const float*)d_in[15];
    float* out = (float*)d_out;

    // opt-in to dynamic smem for every GEMM entry point
    cudaFuncSetAttribute(hgemm_kernel<B_RBFS, B_W1S, B_NONE, B_T1S, 1, false, S_TAB, KPG>,
                         cudaFuncAttributeMaxDynamicSharedMemorySize, (int)SMEM_SZ);
    cudaFuncSetAttribute(hgemm_fused3,
                         cudaFuncAttributeMaxDynamicSharedMemorySize, (int)SMEM_SZ);
    cudaFuncSetAttribute(hgemm_kernel<B_AGGS, B_L2WS, B_NONE, B_X1S, 1, false, N_ATOMS, KP>,
                         cudaFuncAttributeMaxDynamicSharedMemorySize, (int)SMEM_SZ);
    cudaFuncSetAttribute(hgemm_kernel<B_X1S, B_ILWS, B_H, B_HS, 3, false, N_ATOMS, KP>,
                         cudaFuncAttributeMaxDynamicSharedMemorySize, (int)SMEM_SZ);
    cudaFuncSetAttribute(hgemm_kernel<B_POOLS, B_PWS, B_PARAM, B_NONE, 0, false, N_BATCH, KP>,
                         cudaFuncAttributeMaxDynamicSharedMemorySize, (int)SMEM_SZ);

    edge_geom_kernel<<<(N_EDGES + 255) / 256, 256>>>(pos, ei);
    rbf_table_kernel<<<(S_TAB + 255) / 256, 256>>>();
    embed_kernel<<<(N_ATOMS * H4 + 255) / 256, 256>>>(z, emb);
    zero_pool_kernel<<<(N_BATCH * H4 + 255) / 256, 256>>>();
    {
        long long tot = (long long)L * 4 * H * H;
        split_w_all_kernel<<<(unsigned)((tot + 255) / 256), 256>>>(
            mlp_w2, lin1_w, lin2_w, int_lin_w);
        int tot2 = L * G * H + H * H;
        split_w1_pool_kernel<<<(tot2 + 255) / 256, 256>>>(mlp_w1, pool_w);
    }
    // prologue: T1tab(0) into ping-pong slot 0
    hgemm_kernel<B_RBFS, B_W1S, B_NONE, B_T1S, 1, false, S_TAB, KPG>
        <<<dim3(5, NBY_T), 256, SMEM_SZ>>>(mlp_b1, nullptr, 0, 0, 0);

    const dim3 gridN(5, NBY_Y);
    const dim3 gridB(5, 1);
    const int SA_BLK = (N_ATOMS * H4 + 255) / 256;
    const int SC_BLK = (N_EDGES * H4 + 255) / 256;
    const size_t T1SZ = (size_t)S_TAB * KP;

    for (int k = 0; k < L; k++) {
        const float* b2  = mlp_b2    + (size_t)k * H;
        const float* l2b = lin2_b    + (size_t)k * H;
        const float* ilb = int_lin_b + (size_t)k * H;
        const size_t oh  = (size_t)k * KP * H;
        const bool hasNext = (k + 1 < L);
        const float* b1n = hasNext ? (mlp_b1 + (size_t)(k + 1) * H) : nullptr;
        const size_t o1n = hasNext ? (size_t)(k + 1) * KPG * H : 0;
        const size_t t1rd = (size_t)(k & 1) * T1SZ;
        const size_t t1wr = (size_t)((k + 1) & 1) * T1SZ;

        // fused: Y(k)+zero_agg | Wtab(k) | T1tab(k+1)
        int gy = NBY_Y + NBY_T + (hasNext ? NBY_T : 0);
        hgemm_fused3<<<dim3(5, gy), 256, SMEM_SZ>>>(
            b2, b1n, oh, oh, o1n, t1rd, t1wr);
        // agg = scatter_add(Y[src] * lerp(Wtab, d_e), dst)
        scatter_kernel<<<SC_BLK, 256>>>(ei);
        split_act_kernel<B_AGG, B_AGGS><<<SA_BLK, 256>>>(N_ATOMS);
        // x1s = split(ssp(agg @ lin2_w + lin2_b))
        hgemm_kernel<B_AGGS, B_L2WS, B_NONE, B_X1S, 1, false, N_ATOMS, KP>
            <<<gridN, 256, SMEM_SZ>>>(l2b, nullptr, 0, oh, 0);
        // h = h + (x1 @ int_lin_w + int_lin_b); also refresh hs
        hgemm_kernel<B_X1S, B_ILWS, B_H, B_HS, 3, false, N_ATOMS, KP>
            <<<gridN, 256, SMEM_SZ>>>(ilb, nullptr, 0, oh, 0);
    }

    pool_sum_kernel<<<(N_ATOMS * H4 + 255) / 256, 256>>>(batch);
    pool_divsplit_kernel<<<(N_BATCH * H + 255) / 256, 256>>>();
    hgemm_kernel<B_POOLS, B_PWS, B_PARAM, B_NONE, 0, false, N_BATCH, KP>
        <<<gridB, 256, SMEM_SZ>>>(pool_b, out, 0, 0, 0);
}

// round 12
// speedup vs baseline: 1.0461x; 1.0461x over previous
#include <cuda_runtime.h>
#include <cuda_bf16.h>
#include <math.h>
#include <stdint.h>

// ---------------- problem constants ----------------
constexpr int N_ATOMS = 10000;
constexpr int N_EDGES = 64000;
constexpr int N_BATCH = 128;
constexpr int H = 600;
constexpr int H4 = H / 4;
constexpr int G = 50;
constexpr int L = 6;
constexpr float CUTOFF = 10.0f;
constexpr float LN2 = 0.69314718055994530942f;

constexpr int KP  = 1824;   // padded 3*H (multiple of 32)
constexpr int KPG = 160;    // padded 3*G (multiple of 32)
constexpr int S_TAB = 1024; // distance table rows
constexpr float DMAX = 8.66035f;

// ---------------- scratch (device globals, zero-initialized) ----------------
__device__ __nv_bfloat16 g_rbf_s[(size_t)S_TAB * KPG];
__device__ float         g_Ct[S_TAB];
__device__ int           g_ei0[N_EDGES];
__device__ float         g_ef[N_EDGES];
__device__ float         g_h[N_ATOMS * H];
__device__ __nv_bfloat16 g_hs[(size_t)N_ATOMS * KP];
__device__ __nv_bfloat16 g_T1s[2 * (size_t)S_TAB * KP];   // ping-pong T1 table
__device__ float         g_Wtab[(size_t)S_TAB * H];
__device__ float         g_Y[N_ATOMS * H];
__device__ float         g_agg[N_ATOMS * H];
__device__ __nv_bfloat16 g_aggs[(size_t)N_ATOMS * KP];
__device__ __nv_bfloat16 g_x1s[(size_t)N_ATOMS * KP];
__device__ float         g_pooled[N_BATCH * H];
__device__ __nv_bfloat16 g_pooled_s[(size_t)N_BATCH * KP];
__device__ float         g_cnt[N_BATCH];
// split weights for ALL layers (written once per launch, before the loop)
__device__ __nv_bfloat16 g_w1s[(size_t)L * KPG * H];
__device__ __nv_bfloat16 g_w2s[(size_t)L * KP * H];
__device__ __nv_bfloat16 g_l1ws[(size_t)L * KP * H];
__device__ __nv_bfloat16 g_l2ws[(size_t)L * KP * H];
__device__ __nv_bfloat16 g_ilws[(size_t)L * KP * H];
__device__ __nv_bfloat16 g_pws[(size_t)KP * H];

// ---------------- compile-time buffer picker ----------------
enum BufId { B_NONE = -1,
             B_RBFS = 0, B_T1S, B_HS, B_AGGS, B_X1S, B_POOLS,
             B_W1S, B_W2S, B_L1WS, B_L2WS, B_ILWS, B_PWS,
             B_WTAB, B_Y, B_H, B_AGG, B_POOLED, B_PARAM };

template <int B>
__device__ __forceinline__ __nv_bfloat16* bbuf() {
    if constexpr (B == B_RBFS)       return g_rbf_s;
    else if constexpr (B == B_T1S)   return g_T1s;
    else if constexpr (B == B_HS)    return g_hs;
    else if constexpr (B == B_AGGS)  return g_aggs;
    else if constexpr (B == B_X1S)   return g_x1s;
    else if constexpr (B == B_POOLS) return g_pooled_s;
    else if constexpr (B == B_W1S)   return g_w1s;
    else if constexpr (B == B_W2S)   return g_w2s;
    else if constexpr (B == B_L1WS)  return g_l1ws;
    else if constexpr (B == B_L2WS)  return g_l2ws;
    else if constexpr (B == B_ILWS)  return g_ilws;
    else return g_pws;
}
template <int B>
__device__ __forceinline__ float* fbuf(float* p) {
    if constexpr (B == B_WTAB)        return g_Wtab;
    else if constexpr (B == B_Y)      return g_Y;
    else if constexpr (B == B_H)      return g_h;
    else if constexpr (B == B_AGG)    return g_agg;
    else if constexpr (B == B_POOLED) return g_pooled;
    else return p;
}

// ---------------- helpers ----------------
__device__ __forceinline__ float sspf(float x) {
    return fmaxf(x, 0.0f) + log1pf(expf(-fabsf(x))) - LN2;
}
__device__ __forceinline__ void split2(float v, __nv_bfloat16& hi, __nv_bfloat16& lo) {
    hi = __float2bfloat16(v);
    lo = __float2bfloat16(v - __bfloat162float(hi));
}
// split 4 values; write hi x4 / lo x4 / hi x4 (8B each) into split layout
__device__ __forceinline__ void split_store4(__nv_bfloat16* dst, size_t base,
                                             int k, float4 v) {
    __nv_bfloat16 h0, l0, h1, l1, h2, l2, h3, l3;
    split2(v.x, h0, l0); split2(v.y, h1, l1);
    split2(v.z, h2, l2); split2(v.w, h3, l3);
    __nv_bfloat162 hp0 = {h0, h1}, hp1 = {h2, h3};
    __nv_bfloat162 lp0 = {l0, l1}, lp1 = {l2, l3};
    *(uint2*)(dst + base + k) =
        make_uint2(*(uint32_t*)&hp0, *(uint32_t*)&hp1);
    *(uint2*)(dst + base + H + k) =
        make_uint2(*(uint32_t*)&lp0, *(uint32_t*)&lp1);
    *(uint2*)(dst + base + 2 * H + k) =
        make_uint2(*(uint32_t*)&hp0, *(uint32_t*)&hp1);
}

// ---------------- edge geometry ----------------
__global__ void edge_geom_kernel(const float* __restrict__ pos,
                                 const int* __restrict__ ei) {
    int e = blockIdx.x * blockDim.x + threadIdx.x;
    if (e >= N_EDGES) return;
    int s = ei[e];
    int d = ei[N_EDGES + e];
    float dx = pos[s * 3 + 0] - pos[d * 3 + 0];
    float dy = pos[s * 3 + 1] - pos[d * 3 + 1];
    float dz = pos[s * 3 + 2] - pos[d * 3 + 2];
    float dist = sqrtf(dx * dx + dy * dy + dz * dz + 1e-12f);
    float x = dist * ((float)(S_TAB - 1) / DMAX);
    int i0 = (int)x;
    if (i0 > S_TAB - 2) i0 = S_TAB - 2;
    g_ei0[e] = i0;
    g_ef[e] = x - (float)i0;
}

// ---------------- rbf table ----------------
__global__ void rbf_table_kernel() {
    int i = blockIdx.x * blockDim.x + threadIdx.x;
    if (i >= S_TAB) return;
    float dist = (float)i * (DMAX / (float)(S_TAB - 1));
    g_Ct[i] = 0.5f * (cosf(dist * (3.14159265358979323846f / CUTOFF)) + 1.0f);
    const float step = CUTOFF / (float)(G - 1);
    const float coeff = -0.5f / (step * step);
    size_t base = (size_t)i * KPG;
    #pragma unroll
    for (int g = 0; g < G; g++) {
        float t = dist - step * (float)g;
        float v = expf(coeff * t * t);
        __nv_bfloat16 hi, lo; split2(v, hi, lo);
        g_rbf_s[base + g]         = hi;
        g_rbf_s[base + G + g]     = lo;
        g_rbf_s[base + 2 * G + g] = hi;
    }
}

// ---------------- embedding gather (vectorized) ----------------
__global__ void embed_kernel(const int* __restrict__ z,
                             const float* __restrict__ emb) {
    int idx = blockIdx.x * blockDim.x + threadIdx.x;
    const int total = N_ATOMS * H4;
    if (idx >= total) return;
    int i = idx / H4;
    int c4 = idx - i * H4;
    int k = c4 * 4;
    float4 v = *(const float4*)(emb + (size_t)__ldg(&z[i]) * H + k);
    *(float4*)(g_h + (size_t)i * H + k) = v;
    split_store4(g_hs, (size_t)i * KP, k, v);
}

// ---------------- split ALL H x H layer weights ----------------
__global__ void split_w_all_kernel(const float* __restrict__ w2,
                                   const float* __restrict__ l1w,
                                   const float* __restrict__ l2w,
                                   const float* __restrict__ ilw) {
    long long idx = (long long)blockIdx.x * blockDim.x + threadIdx.x;
    const int per = H * H;
    const long long total = (long long)L * 4 * per;
    if (idx >= total) return;
    int t = (int)(idx / per);
    int j = (int)(idx - (long long)t * per);
    int layer = t >> 2, which = t & 3;
    const float* src = ((which == 0) ? w2 : (which == 1) ? l1w
                      : (which == 2) ? l2w : ilw) + (size_t)layer * per;
    __nv_bfloat16* dst = ((which == 0) ? g_w2s : (which == 1) ? g_l1ws
                        : (which == 2) ? g_l2ws : g_ilws) + (size_t)layer * KP * H;
    int r = j / H, n = j - r * H;
    __nv_bfloat16 hi, lo; split2(src[j], hi, lo);
    dst[(size_t)r * H + n]           = hi;
    dst[(size_t)(H + r) * H + n]     = hi;
    dst[(size_t)(2 * H + r) * H + n] = lo;
}

__global__ void split_w1_pool_kernel(const float* __restrict__ w1,
                                     const float* __restrict__ pw) {
    int idx = blockIdx.x * blockDim.x + threadIdx.x;
    const int tot1 = L * G * H;
    if (idx < tot1) {
        int layer = idx / (G * H);
        int j = idx - layer * (G * H);
        int r = j / H, n = j - r * H;
        __nv_bfloat16 hi, lo; split2(w1[idx], hi, lo);
        __nv_bfloat16* dst = g_w1s + (size_t)layer * KPG * H;
        dst[(size_t)r * H + n]           = hi;
        dst[(size_t)(G + r) * H + n]     = hi;
        dst[(size_t)(2 * G + r) * H + n] = lo;
    }
    int idx2 = idx - tot1;
    if (idx2 >= 0 && idx2 < H * H) {
        int r = idx2 / H, n = idx2 - r * H;
        __nv_bfloat16 hi, lo; split2(pw[idx2], hi, lo);
        g_pws[(size_t)r * H + n]           = hi;
        g_pws[(size_t)(H + r) * H + n]     = hi;
        g_pws[(size_t)(2 * H + r) * H + n] = lo;
    }
}

// ---------------- activation split (vectorized) ----------------
template <int SRCF, int DSTB>
__global__ void split_act_kernel(int M) {
    const float* src = fbuf<SRCF>(nullptr);
    __nv_bfloat16* dst = bbuf<DSTB>();
    int idx = blockIdx.x * blockDim.x + threadIdx.x;
    int total = M * H4;
    if (idx >= total) return;
    int m = idx / H4;
    int c4 = idx - m * H4;
    int k = c4 * 4;
    float4 v = *(const float4*)(src + (size_t)m * H + k);
    split_store4(dst, (size_t)m * KP, k, v);
}

// ---------------- pooling small kernels ----------------
__global__ void zero_pool_kernel() {
    int idx = blockIdx.x * blockDim.x + threadIdx.x;
    if (idx < N_BATCH * H4)
        ((float4*)g_pooled)[idx] = make_float4(0.f, 0.f, 0.f, 0.f);
    if (idx < N_BATCH) g_cnt[idx] = 0.0f;
}
// pool_sum with integrated count
__global__ void pool_sum_kernel(const int* __restrict__ batch) {
    int idx = blockIdx.x * blockDim.x + threadIdx.x;
    const int total = N_ATOMS * H4;
    if (idx >= total) return;
    int i = idx / H4;
    int c4 = idx - i * H4;
    int b = __ldg(&batch[i]);
    if (c4 == 0) atomicAdd(&g_cnt[b], 1.0f);
    const float4 v = *(const float4*)(g_h + (size_t)i * H + c4 * 4);
    float* dst = g_pooled + (size_t)b * H + c4 * 4;
    asm volatile("red.global.v4.f32.add [%0], {%1,%2,%3,%4};"
                 :: "l"(dst), "f"(v.x), "f"(v.y), "f"(v.z), "f"(v.w) : "memory");
}
// divide by count AND write split in one pass
__global__ void pool_divsplit_kernel() {
    int idx = blockIdx.x * blockDim.x + threadIdx.x;
    if (idx >= N_BATCH * H) return;
    int b = idx / H, c = idx - b * H;
    float v = g_pooled[idx] / fmaxf(g_cnt[b], 1.0f);
    __nv_bfloat16 hi, lo; split2(v, hi, lo);
    size_t base = (size_t)b * KP;
    g_pooled_s[base + c]         = hi;
    g_pooled_s[base + H + c]     = lo;
    g_pooled_s[base + 2 * H + c] = hi;
}

// ---------------- HMMA GEMM body (3-stage cp.async pipeline) ----------------
constexpr int GBM = 128, GBN = 128, GBK = 32;
constexpr int APAD = 8, BPAD = 8;
constexpr int AST = GBK + APAD;
constexpr int BST = GBN + BPAD;
constexpr uint32_t A_BYTES = GBM * AST * 2;
constexpr uint32_t B_BYTES = GBK * BST * 2;
constexpr uint32_t STG_BYTES = A_BYTES + B_BYTES;
constexpr int NSTAGE = 3;
constexpr uint32_t SMEM_SZ = NSTAGE * STG_BYTES;        // 56832

#define MMA16816(ac, A0, A1, A2, A3, B0, B1)                              \
    asm volatile(                                                         \
        "mma.sync.aligned.m16n8k16.row.col.f32.bf16.bf16.f32 "            \
        "{%0,%1,%2,%3},{%4,%5,%6,%7},{%8,%9},{%0,%1,%2,%3};\n"            \
        : "+f"(ac[0]), "+f"(ac[1]), "+f"(ac[2]), "+f"(ac[3])              \
        : "r"(A0), "r"(A1), "r"(A2), "r"(A3), "r"(B0), "r"(B1))

// EPI: 0 = +bias, 1 = ssp(+bias), 2 = (+bias)*g_Ct[m], 3 = +bias + g_h[m,n]
// ZAGG: epilogue also zeroes g_agg[gm,gn]
template <int ABUF, int BBUF, int CF32, int CSPL, int EPI, bool ZAGG,
          int M_, int KPA_>
__device__ __forceinline__
void gemm_body(const float* __restrict__ bias, float* out_param,
               size_t aoff, size_t boff, size_t csoff, int by) {
    const __nv_bfloat16* __restrict__ A  = bbuf<ABUF>() + aoff;
    const __nv_bfloat16* __restrict__ Bw = bbuf<BBUF>() + boff;
    float* Cf = nullptr;
    if constexpr (CF32 != B_NONE) Cf = fbuf<CF32>(out_param);
    __nv_bfloat16* Cs = nullptr;
    if constexpr (CSPL != B_NONE) Cs = bbuf<CSPL>() + csoff;

    extern __shared__ char dsm[];
    uint32_t sb;
    asm("{ .reg .u64 t; cvta.to.shared.u64 t, %1; cvt.u32.u64 %0, t; }"
        : "=r"(sb) : "l"(dsm));

    const int tid = threadIdx.x;
    const int lane = tid & 31, wid = tid >> 5;
    const int wm = (wid >> 1) * 32;
    const int wn = (wid & 1) * 64;
    const int bm = by * GBM, bn = blockIdx.x * GBN;

    float acc[2][8][4];
    #pragma unroll
    for (int mi = 0; mi < 2; mi++)
        #pragma unroll
        for (int ni = 0; ni < 8; ni++)
            #pragma unroll
            for (int c = 0; c < 4; c++) acc[mi][ni][c] = 0.0f;

    constexpr int KT = KPA_ / GBK;

    auto load_tiles = [&](int kt, int st) {
        int k0 = kt * GBK;
        uint32_t abase = sb + st * STG_BYTES;
        uint32_t bbase = abase + A_BYTES;
        #pragma unroll
        for (int c0 = 0; c0 < 2; c0++) {
            int c = tid + c0 * 256;
            int m = c >> 2, kc = (c & 3) * 8;
            const __nv_bfloat16* src = A + (size_t)(bm + m) * KPA_ + k0 + kc;
            uint32_t dst = abase + (m * AST + kc) * 2;
            int sz = (bm + m < M_) ? 16 : 0;
            asm volatile("cp.async.cg.shared.global [%0],[%1],16,%2;\n"
                         :: "r"(dst), "l"(src), "r"(sz));
        }
        #pragma unroll
        for (int c0 = 0; c0 < 2; c0++) {
            int c = tid + c0 * 256;
            int k = c >> 4, nc = (c & 15) * 8;
            const __nv_bfloat16* src = Bw + (size_t)(k0 + k) * H + bn + nc;
            uint32_t dst = bbase + (k * BST + nc) * 2;
            int sz = (bn + nc < H) ? 16 : 0;
            asm volatile("cp.async.cg.shared.global [%0],[%1],16,%2;\n"
                         :: "r"(dst), "l"(src), "r"(sz));
        }
        asm volatile("cp.async.commit_group;\n");
    };

    constexpr int npre = (KT < NSTAGE) ? KT : NSTAGE;
    #pragma unroll
    for (int s = 0; s < npre; s++) load_tiles(s, s);

    #pragma unroll 1
    for (int kt = 0; kt < KT; kt++) {
        int remaining = KT - 1 - kt;
        if (remaining >= 2)      asm volatile("cp.async.wait_group 2;\n");
        else if (remaining == 1) asm volatile("cp.async.wait_group 1;\n");
        else                     asm volatile("cp.async.wait_group 0;\n");
        __syncthreads();

        int st = kt % NSTAGE;
        uint32_t abase = sb + st * STG_BYTES;
        uint32_t bbase = abase + A_BYTES;

        #pragma unroll
        for (int ks = 0; ks < 2; ks++) {
            const int kk = ks * 16;
            uint32_t a[2][4], b[4][4];
            #pragma unroll
            for (int mi = 0; mi < 2; mi++) {
                int row = wm + mi * 16 + (lane & 15);
                int col = kk + (lane >> 4) * 8;
                uint32_t addr = abase + (row * AST + col) * 2;
                asm volatile("ldmatrix.sync.aligned.m8n8.x4.shared.b16 {%0,%1,%2,%3},[%4];\n"
                             : "=r"(a[mi][0]), "=r"(a[mi][1]), "=r"(a[mi][2]), "=r"(a[mi][3])
                             : "r"(addr));
            }
            #pragma unroll
            for (int ng = 0; ng < 4; ng++) {
                int row = kk + (lane & 15);
                int col = wn + ng * 16 + (lane >> 4) * 8;
                uint32_t addr = bbase + (row * BST + col) * 2;
                asm volatile("ldmatrix.sync.aligned.m8n8.x4.trans.shared.b16 {%0,%1,%2,%3},[%4];\n"
                             : "=r"(b[ng][0]), "=r"(b[ng][1]), "=r"(b[ng][2]), "=r"(b[ng][3])
                             : "r"(addr));
            }
            #pragma unroll
            for (int mi = 0; mi < 2; mi++)
                #pragma unroll
                for (int ni = 0; ni < 8; ni++) {
                    uint32_t b0 = b[ni >> 1][(ni & 1) * 2 + 0];
                    uint32_t b1 = b[ni >> 1][(ni & 1) * 2 + 1];
                    MMA16816(acc[mi][ni], a[mi][0], a[mi][1], a[mi][2], a[mi][3], b0, b1);
                }
        }
        __syncthreads();
        if (kt + NSTAGE < KT) load_tiles(kt + NSTAGE, st);
    }

    #pragma unroll
    for (int mi = 0; mi < 2; mi++) {
        #pragma unroll
        for (int r = 0; r < 2; r++) {
            int gm = bm + wm + mi * 16 + (lane >> 2) + r * 8;
            if (gm >= M_) continue;
            float cs = 0.0f;
            if constexpr (EPI == 2) cs = g_Ct[gm];
            #pragma unroll
            for (int ni = 0; ni < 8; ni++) {
                #pragma unroll
                for (int cc = 0; cc < 2; cc++) {
                    int gn = bn + wn + ni * 8 + (lane & 3) * 2 + cc;
                    if (gn >= H) continue;
                    float v = acc[mi][ni][r * 2 + cc];
                    if (bias) v += bias[gn];
                    if constexpr (EPI == 1) v = sspf(v);
                    if constexpr (EPI == 2) v *= cs;
                    if constexpr (EPI == 3) v += g_h[(size_t)gm * H + gn];
                    if constexpr (CF32 != B_NONE) Cf[(size_t)gm * H + gn] = v;
                    if constexpr (ZAGG) g_agg[(size_t)gm * H + gn] = 0.0f;
                    if constexpr (CSPL != B_NONE) {
                        __nv_bfloat16 hi, lo; split2(v, hi, lo);
                        size_t base = (size_t)gm * KP;
                        Cs[base + gn]         = hi;
                        Cs[base + H + gn]     = lo;
                        Cs[base + 2 * H + gn] = hi;
                    }
                }
            }
        }
    }
}

// single-problem GEMM
template <int ABUF, int BBUF, int CF32, int CSPL, int EPI, bool ZAGG,
          int M_, int KPA_>
__global__ __launch_bounds__(256, 2)
void hgemm_kernel(const float* __restrict__ bias, float* out_param,
                  size_t aoff, size_t boff, size_t csoff) {
    gemm_body<ABUF, BBUF, CF32, CSPL, EPI, ZAGG, M_, KPA_>(
        bias, out_param, aoff, boff, csoff, blockIdx.y);
}

// fused launch: [ Y(k) + zero_agg | Wtab(k) | T1tab(k+1) ]
constexpr int NBY_Y = (N_ATOMS + GBM - 1) / GBM;   // 79
constexpr int NBY_T = S_TAB / GBM;                 // 8
__global__ __launch_bounds__(256, 2)
void hgemm_fused3(const float* __restrict__ b2, const float* __restrict__ b1n,
                  size_t offL1, size_t offW2, size_t offW1n,
                  size_t t1rd, size_t t1wr) {
    int by = blockIdx.y;
    if (by < NBY_Y) {
        gemm_body<B_HS, B_L1WS, B_Y, B_NONE, 0, true, N_ATOMS, KP>(
            nullptr, nullptr, 0, offL1, 0, by);
    } else if (by < NBY_Y + NBY_T) {
        gemm_body<B_T1S, B_W2S, B_WTAB, B_NONE, 2, false, S_TAB, KP>(
            b2, nullptr, t1rd, offW2, 0, by - NBY_Y);
    } else {
        gemm_body<B_RBFS, B_W1S, B_NONE, B_T1S, 1, false, S_TAB, KPG>(
            b1n, nullptr, 0, offW1n, t1wr, by - NBY_Y - NBY_T);
    }
}

// ---------------- CFConv scatter: vectorized lerp + red.v4 ----------------
__global__ void scatter_kernel(const int* __restrict__ ei) {
    int idx = blockIdx.x * blockDim.x + threadIdx.x;
    const int total = N_EDGES * H4;
    if (idx >= total) return;
    int e = idx / H4;
    int c4 = idx - e * H4;
    int s  = __ldg(&ei[e]);
    int d  = __ldg(&ei[N_EDGES + e]);
    int i0 = __ldg(&g_ei0[e]);
    float f = __ldg(&g_ef[e]);
    const float4 y  = *(const float4*)(g_Y    + (size_t)s * H        + c4 * 4);
    const float4 w0 = *(const float4*)(g_Wtab + (size_t)i0 * H       + c4 * 4);
    const float4 w1 = *(const float4*)(g_Wtab + (size_t)(i0 + 1) * H + c4 * 4);
    float v0 = y.x * fmaf(f, w1.x - w0.x, w0.x);
    float v1 = y.y * fmaf(f, w1.y - w0.y, w0.y);
    float v2 = y.z * fmaf(f, w1.z - w0.z, w0.z);
    float v3 = y.w * fmaf(f, w1.w - w0.w, w0.w);
    float* dst = g_agg + (size_t)d * H + c4 * 4;
    asm volatile("red.global.v4.f32.add [%0], {%1,%2,%3,%4};"
                 :: "l"(dst), "f"(v0), "f"(v1), "f"(v2), "f"(v3) : "memory");
}

// ---------------- host side ----------------
extern "C" void kernel_launch(void* const* d_in, const int* in_sizes, int n_in,
                              void* d_out, int out_size) {
    const int*   z         = (const int*)  d_in[0];
    const float* pos       = (const float*)d_in[1];
    const int*   batch     = (const int*)  d_in[2];
    const int*   ei        = (const int*)  d_in[3];
    const float* emb       = (const float*)d_in[4];
    const float* mlp_w1    = (const float*)d_in[5];
    const float* mlp_b1    = (const float*)d_in[6];
    const float* mlp_w2    = (const float*)d_in[7];
    const float* mlp_b2    = (const float*)d_in[8];
    const float* lin1_w    = (const float*)d_in[9];
    const float* lin2_w    = (const float*)d_in[10];
    const float* lin2_b    = (const float*)d_in[11];
    const float* int_lin_w = (const float*)d_in[12];
    const float* int_lin_b = (const float*)d_in[13];
    const float* pool_w    = (const float*)d_in[14];
    const float* pool_b    = (const float*)d_in[15];
    float* out = (float*)d_out;

    // opt-in to dynamic smem for every GEMM entry point
    cudaFuncSetAttribute(hgemm_kernel<B_RBFS, B_W1S, B_NONE, B_T1S, 1, false, S_TAB, KPG>,
                         cudaFuncAttributeMaxDynamicSharedMemorySize, (int)SMEM_SZ);
    cudaFuncSetAttribute(hgemm_fused3,
                         cudaFuncAttributeMaxDynamicSharedMemorySize, (int)SMEM_SZ);
    cudaFuncSetAttribute(hgemm_kernel<B_AGGS, B_L2WS, B_NONE, B_X1S, 1, false, N_ATOMS, KP>,
                         cudaFuncAttributeMaxDynamicSharedMemorySize, (int)SMEM_SZ);
    cudaFuncSetAttribute(hgemm_kernel<B_X1S, B_ILWS, B_H, B_HS, 3, false, N_ATOMS, KP>,
                         cudaFuncAttributeMaxDynamicSharedMemorySize, (int)SMEM_SZ);
    cudaFuncSetAttribute(hgemm_kernel<B_POOLS, B_PWS, B_PARAM, B_NONE, 0, false, N_BATCH, KP>,
                         cudaFuncAttributeMaxDynamicSharedMemorySize, (int)SMEM_SZ);

    edge_geom_kernel<<<(N_EDGES + 255) / 256, 256>>>(pos, ei);
    rbf_table_kernel<<<(S_TAB + 255) / 256, 256>>>();
    embed_kernel<<<(N_ATOMS * H4 + 255) / 256, 256>>>(z, emb);
    zero_pool_kernel<<<(N_BATCH * H4 + 255) / 256, 256>>>();
    {
        long long tot = (long long)L * 4 * H * H;
        split_w_all_kernel<<<(unsigned)((tot + 255) / 256), 256>>>(
            mlp_w2, lin1_w, lin2_w, int_lin_w);
        int tot2 = L * G * H + H * H;
        split_w1_pool_kernel<<<(tot2 + 255) / 256, 256>>>(mlp_w1, pool_w);
    }
    // prologue: T1tab(0) into ping-pong slot 0
    hgemm_kernel<B_RBFS, B_W1S, B_NONE, B_T1S, 1, false, S_TAB, KPG>
        <<<dim3(5, NBY_T), 256, SMEM_SZ>>>(mlp_b1, nullptr, 0, 0, 0);

    const dim3 gridN(5, NBY_Y);
    const dim3 gridB(5, 1);
    const int SA_BLK = (N_ATOMS * H4 + 255) / 256;
    const int SC_BLK = (N_EDGES * H4 + 255) / 256;
    const size_t T1SZ = (size_t)S_TAB * KP;

    for (int k = 0; k < L; k++) {
        const float* b2  = mlp_b2    + (size_t)k * H;
        const float* l2b = lin2_b    + (size_t)k * H;
        const float* ilb = int_lin_b + (size_t)k * H;
        const size_t oh  = (size_t)k * KP * H;
        const bool hasNext = (k + 1 < L);
        const float* b1n = hasNext ? (mlp_b1 + (size_t)(k + 1) * H) : nullptr;
        const size_t o1n = hasNext ? (size_t)(k + 1) * KPG * H : 0;
        const size_t t1rd = (size_t)(k & 1) * T1SZ;
        const size_t t1wr = (size_t)((k + 1) & 1) * T1SZ;

        // fused: Y(k)+zero_agg | Wtab(k) | T1tab(k+1)
        int gy = NBY_Y + NBY_T + (hasNext ? NBY_T : 0);
        hgemm_fused3<<<dim3(5, gy), 256, SMEM_SZ>>>(
            b2, b1n, oh, oh, o1n, t1rd, t1wr);
        // agg = scatter_add(Y[src] * lerp(Wtab, d_e), dst)
        scatter_kernel<<<SC_BLK, 256>>>(ei);
        split_act_kernel<B_AGG, B_AGGS><<<SA_BLK, 256>>>(N_ATOMS);
        // x1s = split(ssp(agg @ lin2_w + lin2_b))
        hgemm_kernel<B_AGGS, B_L2WS, B_NONE, B_X1S, 1, false, N_ATOMS, KP>
            <<<gridN, 256, SMEM_SZ>>>(l2b, nullptr, 0, oh, 0);
        // h = h + (x1 @ int_lin_w + int_lin_b); also refresh hs
        hgemm_kernel<B_X1S, B_ILWS, B_H, B_HS, 3, false, N_ATOMS, KP>
            <<<gridN, 256, SMEM_SZ>>>(ilb, nullptr, 0, oh, 0);
    }

    pool_sum_kernel<<<(N_ATOMS * H4 + 255) / 256, 256>>>(batch);
    pool_divsplit_kernel<<<(N_BATCH * H + 255) / 256, 256>>>();
    hgemm_kernel<B_POOLS, B_PWS, B_PARAM, B_NONE, 0, false, N_BATCH, KP>
        <<<gridB, 256, SMEM_SZ>>>(pool_b, out, 0, 0, 0);
}

// round 13
// speedup vs baseline: 1.1000x; 1.0515x over previous
#include <cuda_runtime.h>
#include <cuda_bf16.h>
#include <math.h>
#include <stdint.h>

// ---------------- problem constants ----------------
constexpr int N_ATOMS = 10000;
constexpr int N_EDGES = 64000;
constexpr int N_BATCH = 128;
constexpr int H = 600;
constexpr int H4 = H / 4;
constexpr int G = 50;
constexpr int L = 6;
constexpr float CUTOFF = 10.0f;
constexpr float LN2 = 0.69314718055994530942f;

constexpr int KP  = 1824;   // padded 3*H (multiple of 32)
constexpr int KPG = 160;    // padded 3*G (multiple of 32)
constexpr int S_TAB = 1024; // distance table rows
constexpr float DMAX = 8.66035f;

// ---------------- scratch (device globals, zero-initialized) ----------------
__device__ __nv_bfloat16 g_rbf_s[(size_t)S_TAB * KPG];
__device__ float         g_Ct[S_TAB];
__device__ float         g_h[N_ATOMS * H];
__device__ __nv_bfloat16 g_hs[(size_t)N_ATOMS * KP];
__device__ __nv_bfloat16 g_T1s[2 * (size_t)S_TAB * KP];   // ping-pong T1 table
__device__ float         g_Wtab[(size_t)S_TAB * H];
__device__ float         g_Y[N_ATOMS * H];
__device__ __nv_bfloat16 g_aggs[(size_t)N_ATOMS * KP];
__device__ __nv_bfloat16 g_x1s[(size_t)N_ATOMS * KP];
__device__ float         g_pooled[N_BATCH * H];
__device__ __nv_bfloat16 g_pooled_s[(size_t)N_BATCH * KP];
__device__ float         g_cnt[N_BATCH];
// CSR edge structure (dst-sorted), built once per launch
__device__ int           g_deg[N_ATOMS + 1];   // offsets after scan
__device__ int           g_cur[N_ATOMS];
__device__ int           g_esrc[N_EDGES];
__device__ int           g_ei0s[N_EDGES];
__device__ float         g_efs[N_EDGES];
// split weights for ALL layers
__device__ __nv_bfloat16 g_w1s[(size_t)L * KPG * H];
__device__ __nv_bfloat16 g_w2s[(size_t)L * KP * H];
__device__ __nv_bfloat16 g_l1ws[(size_t)L * KP * H];
__device__ __nv_bfloat16 g_l2ws[(size_t)L * KP * H];
__device__ __nv_bfloat16 g_ilws[(size_t)L * KP * H];
__device__ __nv_bfloat16 g_pws[(size_t)KP * H];

// ---------------- compile-time buffer picker ----------------
enum BufId { B_NONE = -1,
             B_RBFS = 0, B_T1S, B_HS, B_AGGS, B_X1S, B_POOLS,
             B_W1S, B_W2S, B_L1WS, B_L2WS, B_ILWS, B_PWS,
             B_WTAB, B_Y, B_H, B_POOLED, B_PARAM };

template <int B>
__device__ __forceinline__ __nv_bfloat16* bbuf() {
    if constexpr (B == B_RBFS)       return g_rbf_s;
    else if constexpr (B == B_T1S)   return g_T1s;
    else if constexpr (B == B_HS)    return g_hs;
    else if constexpr (B == B_AGGS)  return g_aggs;
    else if constexpr (B == B_X1S)   return g_x1s;
    else if constexpr (B == B_POOLS) return g_pooled_s;
    else if constexpr (B == B_W1S)   return g_w1s;
    else if constexpr (B == B_W2S)   return g_w2s;
    else if constexpr (B == B_L1WS)  return g_l1ws;
    else if constexpr (B == B_L2WS)  return g_l2ws;
    else if constexpr (B == B_ILWS)  return g_ilws;
    else return g_pws;
}
template <int B>
__device__ __forceinline__ float* fbuf(float* p) {
    if constexpr (B == B_WTAB)        return g_Wtab;
    else if constexpr (B == B_Y)      return g_Y;
    else if constexpr (B == B_H)      return g_h;
    else if constexpr (B == B_POOLED) return g_pooled;
    else return p;
}

// ---------------- helpers ----------------
__device__ __forceinline__ float sspf(float x) {
    return fmaxf(x, 0.0f) + log1pf(expf(-fabsf(x))) - LN2;
}
__device__ __forceinline__ void split2(float v, __nv_bfloat16& hi, __nv_bfloat16& lo) {
    hi = __float2bfloat16(v);
    lo = __float2bfloat16(v - __bfloat162float(hi));
}
__device__ __forceinline__ void split_store4(__nv_bfloat16* dst, size_t base,
                                             int k, float4 v) {
    __nv_bfloat16 h0, l0, h1, l1, h2, l2, h3, l3;
    split2(v.x, h0, l0); split2(v.y, h1, l1);
    split2(v.z, h2, l2); split2(v.w, h3, l3);
    __nv_bfloat162 hp0 = {h0, h1}, hp1 = {h2, h3};
    __nv_bfloat162 lp0 = {l0, l1}, lp1 = {l2, l3};
    *(uint2*)(dst + base + k) =
        make_uint2(*(uint32_t*)&hp0, *(uint32_t*)&hp1);
    *(uint2*)(dst + base + H + k) =
        make_uint2(*(uint32_t*)&lp0, *(uint32_t*)&lp1);
    *(uint2*)(dst + base + 2 * H + k) =
        make_uint2(*(uint32_t*)&hp0, *(uint32_t*)&hp1);
}

// ---------------- CSR construction ----------------
__global__ void zero_deg_kernel() {
    int i = blockIdx.x * blockDim.x + threadIdx.x;
    if (i <= N_ATOMS) g_deg[i] = 0;
    if (i < N_ATOMS) g_cur[i] = 0;
}
__global__ void hist_kernel(const int* __restrict__ ei) {
    int e = blockIdx.x * blockDim.x + threadIdx.x;
    if (e < N_EDGES) atomicAdd(&g_deg[ei[N_EDGES + e] + 1], 1);
}
// single-block inclusive scan of g_deg[0..N_ATOMS]
__global__ void scan_kernel() {
    __shared__ int tmp[1024];
    __shared__ int carry;
    int tid = threadIdx.x;
    if (tid == 0) carry = 0;
    __syncthreads();
    for (int base = 0; base <= N_ATOMS; base += 1024) {
        int i = base + tid;
        int v = (i <= N_ATOMS) ? g_deg[i] : 0;
        tmp[tid] = v;
        __syncthreads();
        #pragma unroll
        for (int off = 1; off < 1024; off <<= 1) {
            int t = (tid >= off) ? tmp[tid - off] : 0;
            __syncthreads();
            tmp[tid] += t;
            __syncthreads();
        }
        int out = tmp[tid] + carry;
        if (i <= N_ATOMS) g_deg[i] = out;
        __syncthreads();
        if (tid == 1023) carry = out;
        __syncthreads();
    }
}
// fused edge geometry + dst-sorted reorder
__global__ void edge_reorder_kernel(const float* __restrict__ pos,
                                    const int* __restrict__ ei) {
    int e = blockIdx.x * blockDim.x + threadIdx.x;
    if (e >= N_EDGES) return;
    int s = ei[e];
    int d = ei[N_EDGES + e];
    float dx = pos[s * 3 + 0] - pos[d * 3 + 0];
    float dy = pos[s * 3 + 1] - pos[d * 3 + 1];
    float dz = pos[s * 3 + 2] - pos[d * 3 + 2];
    float dist = sqrtf(dx * dx + dy * dy + dz * dz + 1e-12f);
    float x = dist * ((float)(S_TAB - 1) / DMAX);
    int i0 = (int)x;
    if (i0 > S_TAB - 2) i0 = S_TAB - 2;
    int p = g_deg[d] + atomicAdd(&g_cur[d], 1);
    g_esrc[p] = s;
    g_ei0s[p] = i0;
    g_efs[p]  = x - (float)i0;
}

// ---------------- rbf table ----------------
__global__ void rbf_table_kernel() {
    int i = blockIdx.x * blockDim.x + threadIdx.x;
    if (i >= S_TAB) return;
    float dist = (float)i * (DMAX / (float)(S_TAB - 1));
    g_Ct[i] = 0.5f * (cosf(dist * (3.14159265358979323846f / CUTOFF)) + 1.0f);
    const float step = CUTOFF / (float)(G - 1);
    const float coeff = -0.5f / (step * step);
    size_t base = (size_t)i * KPG;
    #pragma unroll
    for (int g = 0; g < G; g++) {
        float t = dist - step * (float)g;
        float v = expf(coeff * t * t);
        __nv_bfloat16 hi, lo; split2(v, hi, lo);
        g_rbf_s[base + g]         = hi;
        g_rbf_s[base + G + g]     = lo;
        g_rbf_s[base + 2 * G + g] = hi;
    }
}

// ---------------- embedding gather (vectorized) ----------------
__global__ void embed_kernel(const int* __restrict__ z,
                             const float* __restrict__ emb) {
    int idx = blockIdx.x * blockDim.x + threadIdx.x;
    const int total = N_ATOMS * H4;
    if (idx >= total) return;
    int i = idx / H4;
    int c4 = idx - i * H4;
    int k = c4 * 4;
    float4 v = *(const float4*)(emb + (size_t)__ldg(&z[i]) * H + k);
    *(float4*)(g_h + (size_t)i * H + k) = v;
    split_store4(g_hs, (size_t)i * KP, k, v);
}

// ---------------- split ALL H x H layer weights ----------------
__global__ void split_w_all_kernel(const float* __restrict__ w2,
                                   const float* __restrict__ l1w,
                                   const float* __restrict__ l2w,
                                   const float* __restrict__ ilw) {
    long long idx = (long long)blockIdx.x * blockDim.x + threadIdx.x;
    const int per = H * H;
    const long long total = (long long)L * 4 * per;
    if (idx >= total) return;
    int t = (int)(idx / per);
    int j = (int)(idx - (long long)t * per);
    int layer = t >> 2, which = t & 3;
    const float* src = ((which == 0) ? w2 : (which == 1) ? l1w
                      : (which == 2) ? l2w : ilw) + (size_t)layer * per;
    __nv_bfloat16* dst = ((which == 0) ? g_w2s : (which == 1) ? g_l1ws
                        : (which == 2) ? g_l2ws : g_ilws) + (size_t)layer * KP * H;
    int r = j / H, n = j - r * H;
    __nv_bfloat16 hi, lo; split2(src[j], hi, lo);
    dst[(size_t)r * H + n]           = hi;
    dst[(size_t)(H + r) * H + n]     = hi;
    dst[(size_t)(2 * H + r) * H + n] = lo;
}

__global__ void split_w1_pool_kernel(const float* __restrict__ w1,
                                     const float* __restrict__ pw) {
    int idx = blockIdx.x * blockDim.x + threadIdx.x;
    const int tot1 = L * G * H;
    if (idx < tot1) {
        int layer = idx / (G * H);
        int j = idx - layer * (G * H);
        int r = j / H, n = j - r * H;
        __nv_bfloat16 hi, lo; split2(w1[idx], hi, lo);
        __nv_bfloat16* dst = g_w1s + (size_t)layer * KPG * H;
        dst[(size_t)r * H + n]           = hi;
        dst[(size_t)(G + r) * H + n]     = hi;
        dst[(size_t)(2 * G + r) * H + n] = lo;
    }
    int idx2 = idx - tot1;
    if (idx2 >= 0 && idx2 < H * H) {
        int r = idx2 / H, n = idx2 - r * H;
        __nv_bfloat16 hi, lo; split2(pw[idx2], hi, lo);
        g_pws[(size_t)r * H + n]           = hi;
        g_pws[(size_t)(H + r) * H + n]     = hi;
        g_pws[(size_t)(2 * H + r) * H + n] = lo;
    }
}

// ---------------- pooling small kernels ----------------
__global__ void zero_pool_kernel() {
    int idx = blockIdx.x * blockDim.x + threadIdx.x;
    if (idx < N_BATCH * H4)
        ((float4*)g_pooled)[idx] = make_float4(0.f, 0.f, 0.f, 0.f);
    if (idx < N_BATCH) g_cnt[idx] = 0.0f;
}
__global__ void pool_sum_kernel(const int* __restrict__ batch) {
    int idx = blockIdx.x * blockDim.x + threadIdx.x;
    const int total = N_ATOMS * H4;
    if (idx >= total) return;
    int i = idx / H4;
    int c4 = idx - i * H4;
    int b = __ldg(&batch[i]);
    if (c4 == 0) atomicAdd(&g_cnt[b], 1.0f);
    const float4 v = *(const float4*)(g_h + (size_t)i * H + c4 * 4);
    float* dst = g_pooled + (size_t)b * H + c4 * 4;
    asm volatile("red.global.v4.f32.add [%0], {%1,%2,%3,%4};"
                 :: "l"(dst), "f"(v.x), "f"(v.y), "f"(v.z), "f"(v.w) : "memory");
}
__global__ void pool_divsplit_kernel() {
    int idx = blockIdx.x * blockDim.x + threadIdx.x;
    if (idx >= N_BATCH * H) return;
    int b = idx / H, c = idx - b * H;
    float v = g_pooled[idx] / fmaxf(g_cnt[b], 1.0f);
    __nv_bfloat16 hi, lo; split2(v, hi, lo);
    size_t base = (size_t)b * KP;
    g_pooled_s[base + c]         = hi;
    g_pooled_s[base + H + c]     = lo;
    g_pooled_s[base + 2 * H + c] = hi;
}

// ---------------- HMMA GEMM body (3-stage cp.async pipeline) ----------------
constexpr int GBM = 128, GBN = 128, GBK = 32;
constexpr int APAD = 8, BPAD = 8;
constexpr int AST = GBK + APAD;
constexpr int BST = GBN + BPAD;
constexpr uint32_t A_BYTES = GBM * AST * 2;
constexpr uint32_t B_BYTES = GBK * BST * 2;
constexpr uint32_t STG_BYTES = A_BYTES + B_BYTES;
constexpr int NSTAGE = 3;
constexpr uint32_t SMEM_SZ = NSTAGE * STG_BYTES;        // 56832

#define MMA16816(ac, A0, A1, A2, A3, B0, B1)                              \
    asm volatile(                                                         \
        "mma.sync.aligned.m16n8k16.row.col.f32.bf16.bf16.f32 "            \
        "{%0,%1,%2,%3},{%4,%5,%6,%7},{%8,%9},{%0,%1,%2,%3};\n"            \
        : "+f"(ac[0]), "+f"(ac[1]), "+f"(ac[2]), "+f"(ac[3])              \
        : "r"(A0), "r"(A1), "r"(A2), "r"(A3), "r"(B0), "r"(B1))

// EPI: 0 = +bias, 1 = ssp(+bias), 2 = (+bias)*g_Ct[m], 3 = +bias + g_h[m,n]
template <int ABUF, int BBUF, int CF32, int CSPL, int EPI, int M_, int KPA_>
__device__ __forceinline__
void gemm_body(const float* __restrict__ bias, float* out_param,
               size_t aoff, size_t boff, size_t csoff, int by) {
    const __nv_bfloat16* __restrict__ A  = bbuf<ABUF>() + aoff;
    const __nv_bfloat16* __restrict__ Bw = bbuf<BBUF>() + boff;
    float* Cf = nullptr;
    if constexpr (CF32 != B_NONE) Cf = fbuf<CF32>(out_param);
    __nv_bfloat16* Cs = nullptr;
    if constexpr (CSPL != B_NONE) Cs = bbuf<CSPL>() + csoff;

    extern __shared__ char dsm[];
    uint32_t sb;
    asm("{ .reg .u64 t; cvta.to.shared.u64 t, %1; cvt.u32.u64 %0, t; }"
        : "=r"(sb) : "l"(dsm));

    const int tid = threadIdx.x;
    const int lane = tid & 31, wid = tid >> 5;
    const int wm = (wid >> 1) * 32;
    const int wn = (wid & 1) * 64;
    const int bm = by * GBM, bn = blockIdx.x * GBN;

    float acc[2][8][4];
    #pragma unroll
    for (int mi = 0; mi < 2; mi++)
        #pragma unroll
        for (int ni = 0; ni < 8; ni++)
            #pragma unroll
            for (int c = 0; c < 4; c++) acc[mi][ni][c] = 0.0f;

    constexpr int KT = KPA_ / GBK;

    auto load_tiles = [&](int kt, int st) {
        int k0 = kt * GBK;
        uint32_t abase = sb + st * STG_BYTES;
        uint32_t bbase = abase + A_BYTES;
        #pragma unroll
        for (int c0 = 0; c0 < 2; c0++) {
            int c = tid + c0 * 256;
            int m = c >> 2, kc = (c & 3) * 8;
            const __nv_bfloat16* src = A + (size_t)(bm + m) * KPA_ + k0 + kc;
            uint32_t dst = abase + (m * AST + kc) * 2;
            int sz = (bm + m < M_) ? 16 : 0;
            asm volatile("cp.async.cg.shared.global [%0],[%1],16,%2;\n"
                         :: "r"(dst), "l"(src), "r"(sz));
        }
        #pragma unroll
        for (int c0 = 0; c0 < 2; c0++) {
            int c = tid + c0 * 256;
            int k = c >> 4, nc = (c & 15) * 8;
            const __nv_bfloat16* src = Bw + (size_t)(k0 + k) * H + bn + nc;
            uint32_t dst = bbase + (k * BST + nc) * 2;
            int sz = (bn + nc < H) ? 16 : 0;
            asm volatile("cp.async.cg.shared.global [%0],[%1],16,%2;\n"
                         :: "r"(dst), "l"(src), "r"(sz));
        }
        asm volatile("cp.async.commit_group;\n");
    };

    constexpr int npre = (KT < NSTAGE) ? KT : NSTAGE;
    #pragma unroll
    for (int s = 0; s < npre; s++) load_tiles(s, s);

    #pragma unroll 1
    for (int kt = 0; kt < KT; kt++) {
        int remaining = KT - 1 - kt;
        if (remaining >= 2)      asm volatile("cp.async.wait_group 2;\n");
        else if (remaining == 1) asm volatile("cp.async.wait_group 1;\n");
        else                     asm volatile("cp.async.wait_group 0;\n");
        __syncthreads();

        int st = kt % NSTAGE;
        uint32_t abase = sb + st * STG_BYTES;
        uint32_t bbase = abase + A_BYTES;

        #pragma unroll
        for (int ks = 0; ks < 2; ks++) {
            const int kk = ks * 16;
            uint32_t a[2][4], b[4][4];
            #pragma unroll
            for (int mi = 0; mi < 2; mi++) {
                int row = wm + mi * 16 + (lane & 15);
                int col = kk + (lane >> 4) * 8;
                uint32_t addr = abase + (row * AST + col) * 2;
                asm volatile("ldmatrix.sync.aligned.m8n8.x4.shared.b16 {%0,%1,%2,%3},[%4];\n"
                             : "=r"(a[mi][0]), "=r"(a[mi][1]), "=r"(a[mi][2]), "=r"(a[mi][3])
                             : "r"(addr));
            }
            #pragma unroll
            for (int ng = 0; ng < 4; ng++) {
                int row = kk + (lane & 15);
                int col = wn + ng * 16 + (lane >> 4) * 8;
                uint32_t addr = bbase + (row * BST + col) * 2;
                asm volatile("ldmatrix.sync.aligned.m8n8.x4.trans.shared.b16 {%0,%1,%2,%3},[%4];\n"
                             : "=r"(b[ng][0]), "=r"(b[ng][1]), "=r"(b[ng][2]), "=r"(b[ng][3])
                             : "r"(addr));
            }
            #pragma unroll
            for (int mi = 0; mi < 2; mi++)
                #pragma unroll
                for (int ni = 0; ni < 8; ni++) {
                    uint32_t b0 = b[ni >> 1][(ni & 1) * 2 + 0];
                    uint32_t b1 = b[ni >> 1][(ni & 1) * 2 + 1];
                    MMA16816(acc[mi][ni], a[mi][0], a[mi][1], a[mi][2], a[mi][3], b0, b1);
                }
        }
        __syncthreads();
        if (kt + NSTAGE < KT) load_tiles(kt + NSTAGE, st);
    }

    #pragma unroll
    for (int mi = 0; mi < 2; mi++) {
        #pragma unroll
        for (int r = 0; r < 2; r++) {
            int gm = bm + wm + mi * 16 + (lane >> 2) + r * 8;
            if (gm >= M_) continue;
            float cs = 0.0f;
            if constexpr (EPI == 2) cs = g_Ct[gm];
            #pragma unroll
            for (int ni = 0; ni < 8; ni++) {
                #pragma unroll
                for (int cc = 0; cc < 2; cc++) {
                    int gn = bn + wn + ni * 8 + (lane & 3) * 2 + cc;
                    if (gn >= H) continue;
                    float v = acc[mi][ni][r * 2 + cc];
                    if (bias) v += bias[gn];
                    if constexpr (EPI == 1) v = sspf(v);
                    if constexpr (EPI == 2) v *= cs;
                    if constexpr (EPI == 3) v += g_h[(size_t)gm * H + gn];
                    if constexpr (CF32 != B_NONE) Cf[(size_t)gm * H + gn] = v;
                    if constexpr (CSPL != B_NONE) {
                        __nv_bfloat16 hi, lo; split2(v, hi, lo);
                        size_t base = (size_t)gm * KP;
                        Cs[base + gn]         = hi;
                        Cs[base + H + gn]     = lo;
                        Cs[base + 2 * H + gn] = hi;
                    }
                }
            }
        }
    }
}

// single-problem GEMM
template <int ABUF, int BBUF, int CF32, int CSPL, int EPI, int M_, int KPA_>
__global__ __launch_bounds__(256, 2)
void hgemm_kernel(const float* __restrict__ bias, float* out_param,
                  size_t aoff, size_t boff, size_t csoff) {
    gemm_body<ABUF, BBUF, CF32, CSPL, EPI, M_, KPA_>(
        bias, out_param, aoff, boff, csoff, blockIdx.y);
}

// fused launch: [ Y(k) | Wtab(k) | T1tab(k+1) ]
constexpr int NBY_Y = (N_ATOMS + GBM - 1) / GBM;   // 79
constexpr int NBY_T = S_TAB / GBM;                 // 8
__global__ __launch_bounds__(256, 2)
void hgemm_fused3(const float* __restrict__ b2, const float* __restrict__ b1n,
                  size_t offL1, size_t offW2, size_t offW1n,
                  size_t t1rd, size_t t1wr) {
    int by = blockIdx.y;
    if (by < NBY_Y) {
        gemm_body<B_HS, B_L1WS, B_Y, B_NONE, 0, N_ATOMS, KP>(
            nullptr, nullptr, 0, offL1, 0, by);
    } else if (by < NBY_Y + NBY_T) {
        gemm_body<B_T1S, B_W2S, B_WTAB, B_NONE, 2, S_TAB, KP>(
            b2, nullptr, t1rd, offW2, 0, by - NBY_Y);
    } else {
        gemm_body<B_RBFS, B_W1S, B_NONE, B_T1S, 1, S_TAB, KPG>(
            b1n, nullptr, 0, offW1n, t1wr, by - NBY_Y - NBY_T);
    }
}

// ---------------- CFConv gather: CSR, lerp, fused split output ----------------
__global__ void gather_kernel() {
    int idx = blockIdx.x * blockDim.x + threadIdx.x;
    const int total = N_ATOMS * H4;
    if (idx >= total) return;
    int i = idx / H4;
    int c4 = idx - i * H4;
    int k = c4 * 4;
    int beg = __ldg(&g_deg[i]);
    int end = __ldg(&g_deg[i + 1]);
    float4 acc = make_float4(0.f, 0.f, 0.f, 0.f);
    for (int j = beg; j < end; j++) {
        int s  = __ldg(&g_esrc[j]);
        int i0 = __ldg(&g_ei0s[j]);
        float f = __ldg(&g_efs[j]);
        const float4 y  = *(const float4*)(g_Y    + (size_t)s * H        + k);
        const float4 w0 = *(const float4*)(g_Wtab + (size_t)i0 * H       + k);
        const float4 w1 = *(const float4*)(g_Wtab + (size_t)(i0 + 1) * H + k);
        acc.x = fmaf(y.x, fmaf(f, w1.x - w0.x, w0.x), acc.x);
        acc.y = fmaf(y.y, fmaf(f, w1.y - w0.y, w0.y), acc.y);
        acc.z = fmaf(y.z, fmaf(f, w1.z - w0.z, w0.z), acc.z);
        acc.w = fmaf(y.w, fmaf(f, w1.w - w0.w, w0.w), acc.w);
    }
    split_store4(g_aggs, (size_t)i * KP, k, acc);
}

// ---------------- host side ----------------
extern "C" void kernel_launch(void* const* d_in, const int* in_sizes, int n_in,
                              void* d_out, int out_size) {
    const int*   z         = (const int*)  d_in[0];
    const float* pos       = (const float*)d_in[1];
    const int*   batch     = (const int*)  d_in[2];
    const int*   ei        = (const int*)  d_in[3];
    const float* emb       = (const float*)d_in[4];
    const float* mlp_w1    = (const float*)d_in[5];
    const float* mlp_b1    = (const float*)d_in[6];
    const float* mlp_w2    = (const float*)d_in[7];
    const float* mlp_b2    = (const float*)d_in[8];
    const float* lin1_w    = (const float*)d_in[9];
    const float* lin2_w    = (const float*)d_in[10];
    const float* lin2_b    = (const float*)d_in[11];
    const float* int_lin_w = (const float*)d_in[12];
    const float* int_lin_b = (const float*)d_in[13];
    const float* pool_w    = (const float*)d_in[14];
    const float* pool_b    = (const float*)d_in[15];
    float* out = (float*)d_out;

    cudaFuncSetAttribute(hgemm_kernel<B_RBFS, B_W1S, B_NONE, B_T1S, 1, S_TAB, KPG>,
                         cudaFuncAttributeMaxDynamicSharedMemorySize, (int)SMEM_SZ);
    cudaFuncSetAttribute(hgemm_fused3,
                         cudaFuncAttributeMaxDynamicSharedMemorySize, (int)SMEM_SZ);
    cudaFuncSetAttribute(hgemm_kernel<B_AGGS, B_L2WS, B_NONE, B_X1S, 1, N_ATOMS, KP>,
                         cudaFuncAttributeMaxDynamicSharedMemorySize, (int)SMEM_SZ);
    cudaFuncSetAttribute(hgemm_kernel<B_X1S, B_ILWS, B_H, B_HS, 3, N_ATOMS, KP>,
                         cudaFuncAttributeMaxDynamicSharedMemorySize, (int)SMEM_SZ);
    cudaFuncSetAttribute(hgemm_kernel<B_POOLS, B_PWS, B_PARAM, B_NONE, 0, N_BATCH, KP>,
                         cudaFuncAttributeMaxDynamicSharedMemorySize, (int)SMEM_SZ);

    // CSR build: zero -> histogram -> scan -> geometry+reorder
    zero_deg_kernel<<<(N_ATOMS + 1 + 255) / 256, 256>>>();
    hist_kernel<<<(N_EDGES + 255) / 256, 256>>>(ei);
    scan_kernel<<<1, 1024>>>();
    edge_reorder_kernel<<<(N_EDGES + 255) / 256, 256>>>(pos, ei);

    rbf_table_kernel<<<(S_TAB + 255) / 256, 256>>>();
    embed_kernel<<<(N_ATOMS * H4 + 255) / 256, 256>>>(z, emb);
    zero_pool_kernel<<<(N_BATCH * H4 + 255) / 256, 256>>>();
    {
        long long tot = (long long)L * 4 * H * H;
        split_w_all_kernel<<<(unsigned)((tot + 255) / 256), 256>>>(
            mlp_w2, lin1_w, lin2_w, int_lin_w);
        int tot2 = L * G * H + H * H;
        split_w1_pool_kernel<<<(tot2 + 255) / 256, 256>>>(mlp_w1, pool_w);
    }
    // prologue: T1tab(0) into ping-pong slot 0
    hgemm_kernel<B_RBFS, B_W1S, B_NONE, B_T1S, 1, S_TAB, KPG>
        <<<dim3(5, NBY_T), 256, SMEM_SZ>>>(mlp_b1, nullptr, 0, 0, 0);

    const dim3 gridN(5, NBY_Y);
    const dim3 gridB(5, 1);
    const int GA_BLK = (N_ATOMS * H4 + 255) / 256;
    const size_t T1SZ = (size_t)S_TAB * KP;

    for (int k = 0; k < L; k++) {
        const float* b2  = mlp_b2    + (size_t)k * H;
        const float* l2b = lin2_b    + (size_t)k * H;
        const float* ilb = int_lin_b + (size_t)k * H;
        const size_t oh  = (size_t)k * KP * H;
        const bool hasNext = (k + 1 < L);
        const float* b1n = hasNext ? (mlp_b1 + (size_t)(k + 1) * H) : nullptr;
        const size_t o1n = hasNext ? (size_t)(k + 1) * KPG * H : 0;
        const size_t t1rd = (size_t)(k & 1) * T1SZ;
        const size_t t1wr = (size_t)((k + 1) & 1) * T1SZ;

        // fused: Y(k) | Wtab(k) | T1tab(k+1)
        int gy = NBY_Y + NBY_T + (hasNext ? NBY_T : 0);
        hgemm_fused3<<<dim3(5, gy), 256, SMEM_SZ>>>(
            b2, b1n, oh, oh, o1n, t1rd, t1wr);
        // aggs = split( gather_csr(Y[src] * lerp(Wtab, d_e)) )
        gather_kernel<<<GA_BLK, 256>>>();
        // x1s = split(ssp(agg @ lin2_w + lin2_b))
        hgemm_kernel<B_AGGS, B_L2WS, B_NONE, B_X1S, 1, N_ATOMS, KP>
            <<<gridN, 256, SMEM_SZ>>>(l2b, nullptr, 0, oh, 0);
        // h = h + (x1 @ int_lin_w + int_lin_b); also refresh hs
        hgemm_kernel<B_X1S, B_ILWS, B_H, B_HS, 3, N_ATOMS, KP>
            <<<gridN, 256, SMEM_SZ>>>(ilb, nullptr, 0, oh, 0);
    }

    pool_sum_kernel<<<(N_ATOMS * H4 + 255) / 256, 256>>>(batch);
    pool_divsplit_kernel<<<(N_BATCH * H + 255) / 256, 256>>>();
    hgemm_kernel<B_POOLS, B_PWS, B_PARAM, B_NONE, 0, N_BATCH, KP>
        <<<gridB, 256, SMEM_SZ>>>(pool_b, out, 0, 0, 0);
}

// round 14
// speedup vs baseline: 1.1875x; 1.0795x over previous
#include <cuda_runtime.h>
#include <cuda_bf16.h>
#include <math.h>
#include <stdint.h>

// ---------------- problem constants ----------------
constexpr int N_ATOMS = 10000;
constexpr int N_EDGES = 64000;
constexpr int N_BATCH = 128;
constexpr int H = 600;
constexpr int H4 = H / 4;
constexpr int G = 50;
constexpr int L = 6;
constexpr float CUTOFF = 10.0f;
constexpr float LN2 = 0.69314718055994530942f;

constexpr int KP  = 1824;   // padded 3*H (multiple of 32)
constexpr int KPG = 160;    // padded 3*G (multiple of 32)
constexpr int S_TAB = 1024; // distance table rows
constexpr float DMAX = 8.66035f;

// ---------------- scratch (device globals, zero-initialized) ----------------
__device__ __nv_bfloat16 g_rbf_s[(size_t)S_TAB * KPG];
__device__ float         g_Ct[S_TAB];
__device__ float         g_h[N_ATOMS * H];
__device__ __nv_bfloat16 g_hs[(size_t)N_ATOMS * KP];
__device__ __nv_bfloat16 g_T1s[2 * (size_t)S_TAB * KP];   // ping-pong T1 table
__device__ float         g_Wtab[(size_t)S_TAB * H];
__device__ float         g_Y[N_ATOMS * H];
__device__ __nv_bfloat16 g_aggs[(size_t)N_ATOMS * KP];
__device__ __nv_bfloat16 g_x1s[(size_t)N_ATOMS * KP];
__device__ float         g_pooled[N_BATCH * H];
__device__ __nv_bfloat16 g_pooled_s[(size_t)N_BATCH * KP];
__device__ float         g_cnt[N_BATCH];
// CSR edge structure (dst-sorted), built once per launch
__device__ int           g_deg[N_ATOMS + 1];   // offsets after scan
__device__ int           g_cur[N_ATOMS];
__device__ int           g_esrc[N_EDGES];
__device__ int           g_ei0s[N_EDGES];
__device__ float         g_efs[N_EDGES];
// split weights for ALL layers
__device__ __nv_bfloat16 g_w1s[(size_t)L * KPG * H];
__device__ __nv_bfloat16 g_w2s[(size_t)L * KP * H];
__device__ __nv_bfloat16 g_l1ws[(size_t)L * KP * H];
__device__ __nv_bfloat16 g_l2ws[(size_t)L * KP * H];
__device__ __nv_bfloat16 g_ilws[(size_t)L * KP * H];
__device__ __nv_bfloat16 g_pws[(size_t)KP * H];

// ---------------- compile-time buffer picker ----------------
enum BufId { B_NONE = -1,
             B_RBFS = 0, B_T1S, B_HS, B_AGGS, B_X1S, B_POOLS,
             B_W1S, B_W2S, B_L1WS, B_L2WS, B_ILWS, B_PWS,
             B_WTAB, B_Y, B_H, B_POOLED, B_PARAM };

template <int B>
__device__ __forceinline__ __nv_bfloat16* bbuf() {
    if constexpr (B == B_RBFS)       return g_rbf_s;
    else if constexpr (B == B_T1S)   return g_T1s;
    else if constexpr (B == B_HS)    return g_hs;
    else if constexpr (B == B_AGGS)  return g_aggs;
    else if constexpr (B == B_X1S)   return g_x1s;
    else if constexpr (B == B_POOLS) return g_pooled_s;
    else if constexpr (B == B_W1S)   return g_w1s;
    else if constexpr (B == B_W2S)   return g_w2s;
    else if constexpr (B == B_L1WS)  return g_l1ws;
    else if constexpr (B == B_L2WS)  return g_l2ws;
    else if constexpr (B == B_ILWS)  return g_ilws;
    else return g_pws;
}
template <int B>
__device__ __forceinline__ float* fbuf(float* p) {
    if constexpr (B == B_WTAB)        return g_Wtab;
    else if constexpr (B == B_Y)      return g_Y;
    else if constexpr (B == B_H)      return g_h;
    else if constexpr (B == B_POOLED) return g_pooled;
    else return p;
}

// ---------------- helpers ----------------
__device__ __forceinline__ float sspf(float x) {
    return fmaxf(x, 0.0f) + log1pf(expf(-fabsf(x))) - LN2;
}
__device__ __forceinline__ void split2(float v, __nv_bfloat16& hi, __nv_bfloat16& lo) {
    hi = __float2bfloat16(v);
    lo = __float2bfloat16(v - __bfloat162float(hi));
}
__device__ __forceinline__ void split_store4(__nv_bfloat16* dst, size_t base,
                                             int k, float4 v) {
    __nv_bfloat16 h0, l0, h1, l1, h2, l2, h3, l3;
    split2(v.x, h0, l0); split2(v.y, h1, l1);
    split2(v.z, h2, l2); split2(v.w, h3, l3);
    __nv_bfloat162 hp0 = {h0, h1}, hp1 = {h2, h3};
    __nv_bfloat162 lp0 = {l0, l1}, lp1 = {l2, l3};
    *(uint2*)(dst + base + k) =
        make_uint2(*(uint32_t*)&hp0, *(uint32_t*)&hp1);
    *(uint2*)(dst + base + H + k) =
        make_uint2(*(uint32_t*)&lp0, *(uint32_t*)&lp1);
    *(uint2*)(dst + base + 2 * H + k) =
        make_uint2(*(uint32_t*)&hp0, *(uint32_t*)&hp1);
}

// ---------------- CSR construction ----------------
__global__ void zero_deg_kernel() {
    int i = blockIdx.x * blockDim.x + threadIdx.x;
    if (i <= N_ATOMS) g_deg[i] = 0;
    if (i < N_ATOMS) g_cur[i] = 0;
}
__global__ void hist_kernel(const int* __restrict__ ei) {
    int e = blockIdx.x * blockDim.x + threadIdx.x;
    if (e < N_EDGES) atomicAdd(&g_deg[ei[N_EDGES + e] + 1], 1);
}
// single-block inclusive scan of g_deg[0..N_ATOMS]
__global__ void scan_kernel() {
    __shared__ int tmp[1024];
    __shared__ int carry;
    int tid = threadIdx.x;
    if (tid == 0) carry = 0;
    __syncthreads();
    for (int base = 0; base <= N_ATOMS; base += 1024) {
        int i = base + tid;
        int v = (i <= N_ATOMS) ? g_deg[i] : 0;
        tmp[tid] = v;
        __syncthreads();
        #pragma unroll
        for (int off = 1; off < 1024; off <<= 1) {
            int t = (tid >= off) ? tmp[tid - off] : 0;
            __syncthreads();
            tmp[tid] += t;
            __syncthreads();
        }
        int out = tmp[tid] + carry;
        if (i <= N_ATOMS) g_deg[i] = out;
        __syncthreads();
        if (tid == 1023) carry = out;
        __syncthreads();
    }
}
// fused edge geometry + dst-sorted reorder
__global__ void edge_reorder_kernel(const float* __restrict__ pos,
                                    const int* __restrict__ ei) {
    int e = blockIdx.x * blockDim.x + threadIdx.x;
    if (e >= N_EDGES) return;
    int s = ei[e];
    int d = ei[N_EDGES + e];
    float dx = pos[s * 3 + 0] - pos[d * 3 + 0];
    float dy = pos[s * 3 + 1] - pos[d * 3 + 1];
    float dz = pos[s * 3 + 2] - pos[d * 3 + 2];
    float dist = sqrtf(dx * dx + dy * dy + dz * dz + 1e-12f);
    float x = dist * ((float)(S_TAB - 1) / DMAX);
    int i0 = (int)x;
    if (i0 > S_TAB - 2) i0 = S_TAB - 2;
    int p = g_deg[d] + atomicAdd(&g_cur[d], 1);
    g_esrc[p] = s;
    g_ei0s[p] = i0;
    g_efs[p]  = x - (float)i0;
}

// ---------------- rbf table ----------------
__global__ void rbf_table_kernel() {
    int i = blockIdx.x * blockDim.x + threadIdx.x;
    if (i >= S_TAB) return;
    float dist = (float)i * (DMAX / (float)(S_TAB - 1));
    g_Ct[i] = 0.5f * (cosf(dist * (3.14159265358979323846f / CUTOFF)) + 1.0f);
    const float step = CUTOFF / (float)(G - 1);
    const float coeff = -0.5f / (step * step);
    size_t base = (size_t)i * KPG;
    #pragma unroll
    for (int g = 0; g < G; g++) {
        float t = dist - step * (float)g;
        float v = expf(coeff * t * t);
        __nv_bfloat16 hi, lo; split2(v, hi, lo);
        g_rbf_s[base + g]         = hi;
        g_rbf_s[base + G + g]     = lo;
        g_rbf_s[base + 2 * G + g] = hi;
    }
}

// ---------------- embedding gather (vectorized) ----------------
__global__ void embed_kernel(const int* __restrict__ z,
                             const float* __restrict__ emb) {
    int idx = blockIdx.x * blockDim.x + threadIdx.x;
    const int total = N_ATOMS * H4;
    if (idx >= total) return;
    int i = idx / H4;
    int c4 = idx - i * H4;
    int k = c4 * 4;
    float4 v = *(const float4*)(emb + (size_t)__ldg(&z[i]) * H + k);
    *(float4*)(g_h + (size_t)i * H + k) = v;
    split_store4(g_hs, (size_t)i * KP, k, v);
}

// ---------------- split ALL H x H layer weights ----------------
__global__ void split_w_all_kernel(const float* __restrict__ w2,
                                   const float* __restrict__ l1w,
                                   const float* __restrict__ l2w,
                                   const float* __restrict__ ilw) {
    long long idx = (long long)blockIdx.x * blockDim.x + threadIdx.x;
    const int per = H * H;
    const long long total = (long long)L * 4 * per;
    if (idx >= total) return;
    int t = (int)(idx / per);
    int j = (int)(idx - (long long)t * per);
    int layer = t >> 2, which = t & 3;
    const float* src = ((which == 0) ? w2 : (which == 1) ? l1w
                      : (which == 2) ? l2w : ilw) + (size_t)layer * per;
    __nv_bfloat16* dst = ((which == 0) ? g_w2s : (which == 1) ? g_l1ws
                        : (which == 2) ? g_l2ws : g_ilws) + (size_t)layer * KP * H;
    int r = j / H, n = j - r * H;
    __nv_bfloat16 hi, lo; split2(src[j], hi, lo);
    dst[(size_t)r * H + n]           = hi;
    dst[(size_t)(H + r) * H + n]     = hi;
    dst[(size_t)(2 * H + r) * H + n] = lo;
}

__global__ void split_w1_pool_kernel(const float* __restrict__ w1,
                                     const float* __restrict__ pw) {
    int idx = blockIdx.x * blockDim.x + threadIdx.x;
    const int tot1 = L * G * H;
    if (idx < tot1) {
        int layer = idx / (G * H);
        int j = idx - layer * (G * H);
        int r = j / H, n = j - r * H;
        __nv_bfloat16 hi, lo; split2(w1[idx], hi, lo);
        __nv_bfloat16* dst = g_w1s + (size_t)layer * KPG * H;
        dst[(size_t)r * H + n]           = hi;
        dst[(size_t)(G + r) * H + n]     = hi;
        dst[(size_t)(2 * G + r) * H + n] = lo;
    }
    int idx2 = idx - tot1;
    if (idx2 >= 0 && idx2 < H * H) {
        int r = idx2 / H, n = idx2 - r * H;
        __nv_bfloat16 hi, lo; split2(pw[idx2], hi, lo);
        g_pws[(size_t)r * H + n]           = hi;
        g_pws[(size_t)(H + r) * H + n]     = hi;
        g_pws[(size_t)(2 * H + r) * H + n] = lo;
    }
}

// ---------------- pooling small kernels ----------------
__global__ void zero_pool_kernel() {
    int idx = blockIdx.x * blockDim.x + threadIdx.x;
    if (idx < N_BATCH * H4)
        ((float4*)g_pooled)[idx] = make_float4(0.f, 0.f, 0.f, 0.f);
    if (idx < N_BATCH) g_cnt[idx] = 0.0f;
}
__global__ void pool_sum_kernel(const int* __restrict__ batch) {
    int idx = blockIdx.x * blockDim.x + threadIdx.x;
    const int total = N_ATOMS * H4;
    if (idx >= total) return;
    int i = idx / H4;
    int c4 = idx - i * H4;
    int b = __ldg(&batch[i]);
    if (c4 == 0) atomicAdd(&g_cnt[b], 1.0f);
    const float4 v = *(const float4*)(g_h + (size_t)i * H + c4 * 4);
    float* dst = g_pooled + (size_t)b * H + c4 * 4;
    asm volatile("red.global.v4.f32.add [%0], {%1,%2,%3,%4};"
                 :: "l"(dst), "f"(v.x), "f"(v.y), "f"(v.z), "f"(v.w) : "memory");
}
__global__ void pool_divsplit_kernel() {
    int idx = blockIdx.x * blockDim.x + threadIdx.x;
    if (idx >= N_BATCH * H) return;
    int b = idx / H, c = idx - b * H;
    float v = g_pooled[idx] / fmaxf(g_cnt[b], 1.0f);
    __nv_bfloat16 hi, lo; split2(v, hi, lo);
    size_t base = (size_t)b * KP;
    g_pooled_s[base + c]         = hi;
    g_pooled_s[base + H + c]     = lo;
    g_pooled_s[base + 2 * H + c] = hi;
}

// ---------------- HMMA GEMM body (3-stage, single-barrier pipeline) ----------
constexpr int GBM = 128, GBN = 128, GBK = 32;
constexpr int APAD = 8, BPAD = 8;
constexpr int AST = GBK + APAD;
constexpr int BST = GBN + BPAD;
constexpr uint32_t A_BYTES = GBM * AST * 2;
constexpr uint32_t B_BYTES = GBK * BST * 2;
constexpr uint32_t STG_BYTES = A_BYTES + B_BYTES;
constexpr int NSTAGE = 3;
constexpr uint32_t SMEM_SZ = NSTAGE * STG_BYTES;        // 56832

#define MMA16816(ac, A0, A1, A2, A3, B0, B1)                              \
    asm volatile(                                                         \
        "mma.sync.aligned.m16n8k16.row.col.f32.bf16.bf16.f32 "            \
        "{%0,%1,%2,%3},{%4,%5,%6,%7},{%8,%9},{%0,%1,%2,%3};\n"            \
        : "+f"(ac[0]), "+f"(ac[1]), "+f"(ac[2]), "+f"(ac[3])              \
        : "r"(A0), "r"(A1), "r"(A2), "r"(A3), "r"(B0), "r"(B1))

// EPI: 0 = +bias, 1 = ssp(+bias), 2 = (+bias)*g_Ct[m], 3 = +bias + g_h[m,n]
template <int ABUF, int BBUF, int CF32, int CSPL, int EPI, int M_, int KPA_>
__device__ __forceinline__
void gemm_body(const float* __restrict__ bias, float* out_param,
               size_t aoff, size_t boff, size_t csoff, int by) {
    const __nv_bfloat16* __restrict__ A  = bbuf<ABUF>() + aoff;
    const __nv_bfloat16* __restrict__ Bw = bbuf<BBUF>() + boff;
    float* Cf = nullptr;
    if constexpr (CF32 != B_NONE) Cf = fbuf<CF32>(out_param);
    __nv_bfloat16* Cs = nullptr;
    if constexpr (CSPL != B_NONE) Cs = bbuf<CSPL>() + csoff;

    extern __shared__ char dsm[];
    uint32_t sb;
    asm("{ .reg .u64 t; cvta.to.shared.u64 t, %1; cvt.u32.u64 %0, t; }"
        : "=r"(sb) : "l"(dsm));

    const int tid = threadIdx.x;
    const int lane = tid & 31, wid = tid >> 5;
    const int wm = (wid >> 1) * 32;
    const int wn = (wid & 1) * 64;
    const int bm = by * GBM, bn = blockIdx.x * GBN;

    float acc[2][8][4];
    #pragma unroll
    for (int mi = 0; mi < 2; mi++)
        #pragma unroll
        for (int ni = 0; ni < 8; ni++)
            #pragma unroll
            for (int c = 0; c < 4; c++) acc[mi][ni][c] = 0.0f;

    constexpr int KT = KPA_ / GBK;

    auto load_tiles = [&](int kt, int st) {
        int k0 = kt * GBK;
        uint32_t abase = sb + st * STG_BYTES;
        uint32_t bbase = abase + A_BYTES;
        #pragma unroll
        for (int c0 = 0; c0 < 2; c0++) {
            int c = tid + c0 * 256;
            int m = c >> 2, kc = (c & 3) * 8;
            const __nv_bfloat16* src = A + (size_t)(bm + m) * KPA_ + k0 + kc;
            uint32_t dst = abase + (m * AST + kc) * 2;
            int sz = (bm + m < M_) ? 16 : 0;
            asm volatile("cp.async.cg.shared.global [%0],[%1],16,%2;\n"
                         :: "r"(dst), "l"(src), "r"(sz));
        }
        #pragma unroll
        for (int c0 = 0; c0 < 2; c0++) {
            int c = tid + c0 * 256;
            int k = c >> 4, nc = (c & 15) * 8;
            const __nv_bfloat16* src = Bw + (size_t)(k0 + k) * H + bn + nc;
            uint32_t dst = bbase + (k * BST + nc) * 2;
            int sz = (bn + nc < H) ? 16 : 0;
            asm volatile("cp.async.cg.shared.global [%0],[%1],16,%2;\n"
                         :: "r"(dst), "l"(src), "r"(sz));
        }
        asm volatile("cp.async.commit_group;\n");
    };

    // prologue: preload NSTAGE-1 stages
    constexpr int npre = (KT < NSTAGE - 1) ? KT : (NSTAGE - 1);
    #pragma unroll
    for (int s = 0; s < npre; s++) load_tiles(s, s);

    #pragma unroll 1
    for (int kt = 0; kt < KT; kt++) {
        int remaining = KT - 1 - kt;
        if (remaining >= 1) asm volatile("cp.async.wait_group 1;\n");
        else                asm volatile("cp.async.wait_group 0;\n");
        __syncthreads();
        // refill the stage freed at iteration kt-1 (reads completed before
        // the barrier above) with data for iteration kt+NSTAGE-1
        if (kt + NSTAGE - 1 < KT)
            load_tiles(kt + NSTAGE - 1, (kt + NSTAGE - 1) % NSTAGE);

        int st = kt % NSTAGE;
        uint32_t abase = sb + st * STG_BYTES;
        uint32_t bbase = abase + A_BYTES;

        #pragma unroll
        for (int ks = 0; ks < 2; ks++) {
            const int kk = ks * 16;
            uint32_t a[2][4], b[4][4];
            #pragma unroll
            for (int mi = 0; mi < 2; mi++) {
                int row = wm + mi * 16 + (lane & 15);
                int col = kk + (lane >> 4) * 8;
                uint32_t addr = abase + (row * AST + col) * 2;
                asm volatile("ldmatrix.sync.aligned.m8n8.x4.shared.b16 {%0,%1,%2,%3},[%4];\n"
                             : "=r"(a[mi][0]), "=r"(a[mi][1]), "=r"(a[mi][2]), "=r"(a[mi][3])
                             : "r"(addr));
            }
            #pragma unroll
            for (int ng = 0; ng < 4; ng++) {
                int row = kk + (lane & 15);
                int col = wn + ng * 16 + (lane >> 4) * 8;
                uint32_t addr = bbase + (row * BST + col) * 2;
                asm volatile("ldmatrix.sync.aligned.m8n8.x4.trans.shared.b16 {%0,%1,%2,%3},[%4];\n"
                             : "=r"(b[ng][0]), "=r"(b[ng][1]), "=r"(b[ng][2]), "=r"(b[ng][3])
                             : "r"(addr));
            }
            #pragma unroll
            for (int mi = 0; mi < 2; mi++)
                #pragma unroll
                for (int ni = 0; ni < 8; ni++) {
                    uint32_t b0 = b[ni >> 1][(ni & 1) * 2 + 0];
                    uint32_t b1 = b[ni >> 1][(ni & 1) * 2 + 1];
                    MMA16816(acc[mi][ni], a[mi][0], a[mi][1], a[mi][2], a[mi][3], b0, b1);
                }
        }
        // no trailing barrier: next iteration's barrier protects stage reuse
    }

    #pragma unroll
    for (int mi = 0; mi < 2; mi++) {
        #pragma unroll
        for (int r = 0; r < 2; r++) {
            int gm = bm + wm + mi * 16 + (lane >> 2) + r * 8;
            if (gm >= M_) continue;
            float cs = 0.0f;
            if constexpr (EPI == 2) cs = g_Ct[gm];
            #pragma unroll
            for (int ni = 0; ni < 8; ni++) {
                #pragma unroll
                for (int cc = 0; cc < 2; cc++) {
                    int gn = bn + wn + ni * 8 + (lane & 3) * 2 + cc;
                    if (gn >= H) continue;
                    float v = acc[mi][ni][r * 2 + cc];
                    if (bias) v += bias[gn];
                    if constexpr (EPI == 1) v = sspf(v);
                    if constexpr (EPI == 2) v *= cs;
                    if constexpr (EPI == 3) v += g_h[(size_t)gm * H + gn];
                    if constexpr (CF32 != B_NONE) Cf[(size_t)gm * H + gn] = v;
                    if constexpr (CSPL != B_NONE) {
                        __nv_bfloat16 hi, lo; split2(v, hi, lo);
                        size_t base = (size_t)gm * KP;
                        Cs[base + gn]         = hi;
                        Cs[base + H + gn]     = lo;
                        Cs[base + 2 * H + gn] = hi;
                    }
                }
            }
        }
    }
}

// single-problem GEMM
template <int ABUF, int BBUF, int CF32, int CSPL, int EPI, int M_, int KPA_>
__global__ __launch_bounds__(256, 2)
void hgemm_kernel(const float* __restrict__ bias, float* out_param,
                  size_t aoff, size_t boff, size_t csoff) {
    gemm_body<ABUF, BBUF, CF32, CSPL, EPI, M_, KPA_>(
        bias, out_param, aoff, boff, csoff, blockIdx.y);
}

// fused launch: [ Y(k) | Wtab(k) | T1tab(k+1) ]
constexpr int NBY_Y = (N_ATOMS + GBM - 1) / GBM;   // 79
constexpr int NBY_T = S_TAB / GBM;                 // 8
__global__ __launch_bounds__(256, 2)
void hgemm_fused3(const float* __restrict__ b2, const float* __restrict__ b1n,
                  size_t offL1, size_t offW2, size_t offW1n,
                  size_t t1rd, size_t t1wr) {
    int by = blockIdx.y;
    if (by < NBY_Y) {
        gemm_body<B_HS, B_L1WS, B_Y, B_NONE, 0, N_ATOMS, KP>(
            nullptr, nullptr, 0, offL1, 0, by);
    } else if (by < NBY_Y + NBY_T) {
        gemm_body<B_T1S, B_W2S, B_WTAB, B_NONE, 2, S_TAB, KP>(
            b2, nullptr, t1rd, offW2, 0, by - NBY_Y);
    } else {
        gemm_body<B_RBFS, B_W1S, B_NONE, B_T1S, 1, S_TAB, KPG>(
            b1n, nullptr, 0, offW1n, t1wr, by - NBY_Y - NBY_T);
    }
}

// ---------------- CFConv gather: CSR, lerp, fused split output ----------------
__global__ void gather_kernel() {
    int idx = blockIdx.x * blockDim.x + threadIdx.x;
    const int total = N_ATOMS * H4;
    if (idx >= total) return;
    int i = idx / H4;
    int c4 = idx - i * H4;
    int k = c4 * 4;
    int beg = __ldg(&g_deg[i]);
    int end = __ldg(&g_deg[i + 1]);
    float4 acc = make_float4(0.f, 0.f, 0.f, 0.f);
    for (int j = beg; j < end; j++) {
        int s  = __ldg(&g_esrc[j]);
        int i0 = __ldg(&g_ei0s[j]);
        float f = __ldg(&g_efs[j]);
        const float4 y  = *(const float4*)(g_Y    + (size_t)s * H        + k);
        const float4 w0 = *(const float4*)(g_Wtab + (size_t)i0 * H       + k);
        const float4 w1 = *(const float4*)(g_Wtab + (size_t)(i0 + 1) * H + k);
        acc.x = fmaf(y.x, fmaf(f, w1.x - w0.x, w0.x), acc.x);
        acc.y = fmaf(y.y, fmaf(f, w1.y - w0.y, w0.y), acc.y);
        acc.z = fmaf(y.z, fmaf(f, w1.z - w0.z, w0.z), acc.z);
        acc.w = fmaf(y.w, fmaf(f, w1.w - w0.w, w0.w), acc.w);
    }
    split_store4(g_aggs, (size_t)i * KP, k, acc);
}

// ---------------- host side ----------------
extern "C" void kernel_launch(void* const* d_in, const int* in_sizes, int n_in,
                              void* d_out, int out_size) {
    const int*   z         = (const int*)  d_in[0];
    const float* pos       = (const float*)d_in[1];
    const int*   batch     = (const int*)  d_in[2];
    const int*   ei        = (const int*)  d_in[3];
    const float* emb       = (const float*)d_in[4];
    const float* mlp_w1    = (const float*)d_in[5];
    const float* mlp_b1    = (const float*)d_in[6];
    const float* mlp_w2    = (const float*)d_in[7];
    const float* mlp_b2    = (const float*)d_in[8];
    const float* lin1_w    = (const float*)d_in[9];
    const float* lin2_w    = (const float*)d_in[10];
    const float* lin2_b    = (const float*)d_in[11];
    const float* int_lin_w = (const float*)d_in[12];
    const float* int_lin_b = (const float*)d_in[13];
    const float* pool_w    = (const float*)d_in[14];
    const float* pool_b    = (const float*)d_in[15];
    float* out = (float*)d_out;

    cudaFuncSetAttribute(hgemm_kernel<B_RBFS, B_W1S, B_NONE, B_T1S, 1, S_TAB, KPG>,
                         cudaFuncAttributeMaxDynamicSharedMemorySize, (int)SMEM_SZ);
    cudaFuncSetAttribute(hgemm_fused3,
                         cudaFuncAttributeMaxDynamicSharedMemorySize, (int)SMEM_SZ);
    cudaFuncSetAttribute(hgemm_kernel<B_AGGS, B_L2WS, B_NONE, B_X1S, 1, N_ATOMS, KP>,
                         cudaFuncAttributeMaxDynamicSharedMemorySize, (int)SMEM_SZ);
    cudaFuncSetAttribute(hgemm_kernel<B_X1S, B_ILWS, B_H, B_HS, 3, N_ATOMS, KP>,
                         cudaFuncAttributeMaxDynamicSharedMemorySize, (int)SMEM_SZ);
    cudaFuncSetAttribute(hgemm_kernel<B_POOLS, B_PWS, B_PARAM, B_NONE, 0, N_BATCH, KP>,
                         cudaFuncAttributeMaxDynamicSharedMemorySize, (int)SMEM_SZ);

    // CSR build: zero -> histogram -> scan -> geometry+reorder
    zero_deg_kernel<<<(N_ATOMS + 1 + 255) / 256, 256>>>();
    hist_kernel<<<(N_EDGES + 255) / 256, 256>>>(ei);
    scan_kernel<<<1, 1024>>>();
    edge_reorder_kernel<<<(N_EDGES + 255) / 256, 256>>>(pos, ei);

    rbf_table_kernel<<<(S_TAB + 255) / 256, 256>>>();
    embed_kernel<<<(N_ATOMS * H4 + 255) / 256, 256>>>(z, emb);
    zero_pool_kernel<<<(N_BATCH * H4 + 255) / 256, 256>>>();
    {
        long long tot = (long long)L * 4 * H * H;
        split_w_all_kernel<<<(unsigned)((tot + 255) / 256), 256>>>(
            mlp_w2, lin1_w, lin2_w, int_lin_w);
        int tot2 = L * G * H + H * H;
        split_w1_pool_kernel<<<(tot2 + 255) / 256, 256>>>(mlp_w1, pool_w);
    }
    // prologue: T1tab(0) into ping-pong slot 0
    hgemm_kernel<B_RBFS, B_W1S, B_NONE, B_T1S, 1, S_TAB, KPG>
        <<<dim3(5, NBY_T), 256, SMEM_SZ>>>(mlp_b1, nullptr, 0, 0, 0);

    const dim3 gridN(5, NBY_Y);
    const dim3 gridB(5, 1);
    const int GA_BLK = (N_ATOMS * H4 + 255) / 256;
    const size_t T1SZ = (size_t)S_TAB * KP;

    for (int k = 0; k < L; k++) {
        const float* b2  = mlp_b2    + (size_t)k * H;
        const float* l2b = lin2_b    + (size_t)k * H;
        const float* ilb = int_lin_b + (size_t)k * H;
        const size_t oh  = (size_t)k * KP * H;
        const bool hasNext = (k + 1 < L);
        const float* b1n = hasNext ? (mlp_b1 + (size_t)(k + 1) * H) : nullptr;
        const size_t o1n = hasNext ? (size_t)(k + 1) * KPG * H : 0;
        const size_t t1rd = (size_t)(k & 1) * T1SZ;
        const size_t t1wr = (size_t)((k + 1) & 1) * T1SZ;

        // fused: Y(k) | Wtab(k) | T1tab(k+1)
        int gy = NBY_Y + NBY_T + (hasNext ? NBY_T : 0);
        hgemm_fused3<<<dim3(5, gy), 256, SMEM_SZ>>>(
            b2, b1n, oh, oh, o1n, t1rd, t1wr);
        // aggs = split( gather_csr(Y[src] * lerp(Wtab, d_e)) )
        gather_kernel<<<GA_BLK, 256>>>();
        // x1s = split(ssp(agg @ lin2_w + lin2_b))
        hgemm_kernel<B_AGGS, B_L2WS, B_NONE, B_X1S, 1, N_ATOMS, KP>
            <<<gridN, 256, SMEM_SZ>>>(l2b, nullptr, 0, oh, 0);
        // h = h + (x1 @ int_lin_w + int_lin_b); also refresh hs
        hgemm_kernel<B_X1S, B_ILWS, B_H, B_HS, 3, N_ATOMS, KP>
            <<<gridN, 256, SMEM_SZ>>>(ilb, nullptr, 0, oh, 0);
    }

    pool_sum_kernel<<<(N_ATOMS * H4 + 255) / 256, 256>>>(batch);
    pool_divsplit_kernel<<<(N_BATCH * H + 255) / 256, 256>>>();
    hgemm_kernel<B_POOLS, B_PWS, B_PARAM, B_NONE, 0, N_BATCH, KP>
        <<<gridB, 256, SMEM_SZ>>>(pool_b, out, 0, 0, 0);
}

// round 16
// speedup vs baseline: 1.4412x; 1.2136x over previous
#include <cuda_runtime.h>
#include <cuda_bf16.h>
#include <math.h>
#include <stdint.h>

// ---------------- problem constants ----------------
constexpr int N_ATOMS = 10000;
constexpr int N_EDGES = 64000;
constexpr int N_BATCH = 128;
constexpr int H = 600;
constexpr int H4 = H / 4;
constexpr int G = 50;
constexpr int L = 6;
constexpr float CUTOFF = 10.0f;
constexpr float LN2 = 0.69314718055994530942f;

constexpr int KP  = 1856;   // padded 3*H (multiple of 64)
constexpr int KPG = 192;    // padded 3*G (multiple of 64)
constexpr int S_TAB = 1024; // distance table rows
constexpr float DMAX = 8.66035f;

// ---------------- scratch (device globals, zero-initialized) ----------------
__device__ __nv_bfloat16 g_rbf_s[(size_t)S_TAB * KPG];
__device__ float         g_Ct[S_TAB];
__device__ float         g_h[N_ATOMS * H];
__device__ __nv_bfloat16 g_hs[(size_t)N_ATOMS * KP];
__device__ __nv_bfloat16 g_T1s[2 * (size_t)S_TAB * KP];   // ping-pong T1 table
__device__ float         g_Wtab[(size_t)S_TAB * H];
__device__ float         g_Y[N_ATOMS * H];
__device__ __nv_bfloat16 g_aggs[(size_t)N_ATOMS * KP];
__device__ __nv_bfloat16 g_x1s[(size_t)N_ATOMS * KP];
__device__ float         g_pooled[N_BATCH * H];
__device__ __nv_bfloat16 g_pooled_s[(size_t)N_BATCH * KP];
__device__ float         g_cnt[N_BATCH];
// CSR edge structure (dst-sorted), built once per launch
__device__ int           g_deg[N_ATOMS + 1];   // offsets after scan
__device__ int           g_cur[N_ATOMS];
__device__ int           g_esrc[N_EDGES];
__device__ int           g_ei0s[N_EDGES];
__device__ float         g_efs[N_EDGES];
// split weights for ALL layers
__device__ __nv_bfloat16 g_w1s[(size_t)L * KPG * H];
__device__ __nv_bfloat16 g_w2s[(size_t)L * KP * H];
__device__ __nv_bfloat16 g_l1ws[(size_t)L * KP * H];
__device__ __nv_bfloat16 g_l2ws[(size_t)L * KP * H];
__device__ __nv_bfloat16 g_ilws[(size_t)L * KP * H];
__device__ __nv_bfloat16 g_pws[(size_t)KP * H];

// ---------------- compile-time buffer picker ----------------
enum BufId { B_NONE = -1,
             B_RBFS = 0, B_T1S, B_HS, B_AGGS, B_X1S, B_POOLS,
             B_W1S, B_W2S, B_L1WS, B_L2WS, B_ILWS, B_PWS,
             B_WTAB, B_Y, B_H, B_POOLED, B_PARAM };

template <int B>
__device__ __forceinline__ __nv_bfloat16* bbuf() {
    if constexpr (B == B_RBFS)       return g_rbf_s;
    else if constexpr (B == B_T1S)   return g_T1s;
    else if constexpr (B == B_HS)    return g_hs;
    else if constexpr (B == B_AGGS)  return g_aggs;
    else if constexpr (B == B_X1S)   return g_x1s;
    else if constexpr (B == B_POOLS) return g_pooled_s;
    else if constexpr (B == B_W1S)   return g_w1s;
    else if constexpr (B == B_W2S)   return g_w2s;
    else if constexpr (B == B_L1WS)  return g_l1ws;
    else if constexpr (B == B_L2WS)  return g_l2ws;
    else if constexpr (B == B_ILWS)  return g_ilws;
    else return g_pws;
}
template <int B>
__device__ __forceinline__ float* fbuf(float* p) {
    if constexpr (B == B_WTAB)        return g_Wtab;
    else if constexpr (B == B_Y)      return g_Y;
    else if constexpr (B == B_H)      return g_h;
    else if constexpr (B == B_POOLED) return g_pooled;
    else return p;
}

// ---------------- helpers ----------------
__device__ __forceinline__ float sspf(float x) {
    return fmaxf(x, 0.0f) + log1pf(expf(-fabsf(x))) - LN2;
}
__device__ __forceinline__ void split2(float v, __nv_bfloat16& hi, __nv_bfloat16& lo) {
    hi = __float2bfloat16(v);
    lo = __float2bfloat16(v - __bfloat162float(hi));
}
__device__ __forceinline__ void split_store4(__nv_bfloat16* dst, size_t base,
                                             int k, float4 v) {
    __nv_bfloat16 h0, l0, h1, l1, h2, l2, h3, l3;
    split2(v.x, h0, l0); split2(v.y, h1, l1);
    split2(v.z, h2, l2); split2(v.w, h3, l3);
    __nv_bfloat162 hp0 = {h0, h1}, hp1 = {h2, h3};
    __nv_bfloat162 lp0 = {l0, l1}, lp1 = {l2, l3};
    *(uint2*)(dst + base + k) =
        make_uint2(*(uint32_t*)&hp0, *(uint32_t*)&hp1);
    *(uint2*)(dst + base + H + k) =
        make_uint2(*(uint32_t*)&lp0, *(uint32_t*)&lp1);
    *(uint2*)(dst + base + 2 * H + k) =
        make_uint2(*(uint32_t*)&hp0, *(uint32_t*)&hp1);
}

// ---------------- CSR construction ----------------
__global__ void zero_deg_kernel() {
    int i = blockIdx.x * blockDim.x + threadIdx.x;
    if (i <= N_ATOMS) g_deg[i] = 0;
    if (i < N_ATOMS) g_cur[i] = 0;
}
__global__ void hist_kernel(const int* __restrict__ ei) {
    int e = blockIdx.x * blockDim.x + threadIdx.x;
    if (e < N_EDGES) atomicAdd(&g_deg[ei[N_EDGES + e] + 1], 1);
}
// single-block inclusive scan of g_deg[0..N_ATOMS]
__global__ void scan_kernel() {
    __shared__ int tmp[1024];
    __shared__ int carry;
    int tid = threadIdx.x;
    if (tid == 0) carry = 0;
    __syncthreads();
    for (int base = 0; base <= N_ATOMS; base += 1024) {
        int i = base + tid;
        int v = (i <= N_ATOMS) ? g_deg[i] : 0;
        tmp[tid] = v;
        __syncthreads();
        #pragma unroll
        for (int off = 1; off < 1024; off <<= 1) {
            int t = (tid >= off) ? tmp[tid - off] : 0;
            __syncthreads();
            tmp[tid] += t;
            __syncthreads();
        }
        int out = tmp[tid] + carry;
        if (i <= N_ATOMS) g_deg[i] = out;
        __syncthreads();
        if (tid == 1023) carry = out;
        __syncthreads();
    }
}
// fused edge geometry + dst-sorted reorder
__global__ void edge_reorder_kernel(const float* __restrict__ pos,
                                    const int* __restrict__ ei) {
    int e = blockIdx.x * blockDim.x + threadIdx.x;
    if (e >= N_EDGES) return;
    int s = ei[e];
    int d = ei[N_EDGES + e];
    float dx = pos[s * 3 + 0] - pos[d * 3 + 0];
    float dy = pos[s * 3 + 1] - pos[d * 3 + 1];
    float dz = pos[s * 3 + 2] - pos[d * 3 + 2];
    float dist = sqrtf(dx * dx + dy * dy + dz * dz + 1e-12f);
    float x = dist * ((float)(S_TAB - 1) / DMAX);
    int i0 = (int)x;
    if (i0 > S_TAB - 2) i0 = S_TAB - 2;
    int p = g_deg[d] + atomicAdd(&g_cur[d], 1);
    g_esrc[p] = s;
    g_ei0s[p] = i0;
    g_efs[p]  = x - (float)i0;
}

// ---------------- rbf table ----------------
__global__ void rbf_table_kernel() {
    int i = blockIdx.x * blockDim.x + threadIdx.x;
    if (i >= S_TAB) return;
    float dist = (float)i * (DMAX / (float)(S_TAB - 1));
    g_Ct[i] = 0.5f * (cosf(dist * (3.14159265358979323846f / CUTOFF)) + 1.0f);
    const float step = CUTOFF / (float)(G - 1);
    const float coeff = -0.5f / (step * step);
    size_t base = (size_t)i * KPG;
    #pragma unroll
    for (int g = 0; g < G; g++) {
        float t = dist - step * (float)g;
        float v = expf(coeff * t * t);
        __nv_bfloat16 hi, lo; split2(v, hi, lo);
        g_rbf_s[base + g]         = hi;
        g_rbf_s[base + G + g]     = lo;
        g_rbf_s[base + 2 * G + g] = hi;
    }
}

// ---------------- embedding gather (vectorized) ----------------
__global__ void embed_kernel(const int* __restrict__ z,
                             const float* __restrict__ emb) {
    int idx = blockIdx.x * blockDim.x + threadIdx.x;
    const int total = N_ATOMS * H4;
    if (idx >= total) return;
    int i = idx / H4;
    int c4 = idx - i * H4;
    int k = c4 * 4;
    float4 v = *(const float4*)(emb + (size_t)__ldg(&z[i]) * H + k);
    *(float4*)(g_h + (size_t)i * H + k) = v;
    split_store4(g_hs, (size_t)i * KP, k, v);
}

// ---------------- split ALL H x H layer weights ----------------
__global__ void split_w_all_kernel(const float* __restrict__ w2,
                                   const float* __restrict__ l1w,
                                   const float* __restrict__ l2w,
                                   const float* __restrict__ ilw) {
    long long idx = (long long)blockIdx.x * blockDim.x + threadIdx.x;
    const int per = H * H;
    const long long total = (long long)L * 4 * per;
    if (idx >= total) return;
    int t = (int)(idx / per);
    int j = (int)(idx - (long long)t * per);
    int layer = t >> 2, which = t & 3;
    const float* src = ((which == 0) ? w2 : (which == 1) ? l1w
                      : (which == 2) ? l2w : ilw) + (size_t)layer * per;
    __nv_bfloat16* dst = ((which == 0) ? g_w2s : (which == 1) ? g_l1ws
                        : (which == 2) ? g_l2ws : g_ilws) + (size_t)layer * KP * H;
    int r = j / H, n = j - r * H;
    __nv_bfloat16 hi, lo; split2(src[j], hi, lo);
    dst[(size_t)r * H + n]           = hi;
    dst[(size_t)(H + r) * H + n]     = hi;
    dst[(size_t)(2 * H + r) * H + n] = lo;
}

__global__ void split_w1_pool_kernel(const float* __restrict__ w1,
                                     const float* __restrict__ pw) {
    int idx = blockIdx.x * blockDim.x + threadIdx.x;
    const int tot1 = L * G * H;
    if (idx < tot1) {
        int layer = idx / (G * H);
        int j = idx - layer * (G * H);
        int r = j / H, n = j - r * H;
        __nv_bfloat16 hi, lo; split2(w1[idx], hi, lo);
        __nv_bfloat16* dst = g_w1s + (size_t)layer * KPG * H;
        dst[(size_t)r * H + n]           = hi;
        dst[(size_t)(G + r) * H + n]     = hi;
        dst[(size_t)(2 * G + r) * H + n] = lo;
    }
    int idx2 = idx - tot1;
    if (idx2 >= 0 && idx2 < H * H) {
        int r = idx2 / H, n = idx2 - r * H;
        __nv_bfloat16 hi, lo; split2(pw[idx2], hi, lo);
        g_pws[(size_t)r * H + n]           = hi;
        g_pws[(size_t)(H + r) * H + n]     = hi;
        g_pws[(size_t)(2 * H + r) * H + n] = lo;
    }
}

// ---------------- pooling small kernels ----------------
__global__ void zero_pool_kernel() {
    int idx = blockIdx.x * blockDim.x + threadIdx.x;
    if (idx < N_BATCH * H4)
        ((float4*)g_pooled)[idx] = make_float4(0.f, 0.f, 0.f, 0.f);
    if (idx < N_BATCH) g_cnt[idx] = 0.0f;
}
__global__ void pool_sum_kernel(const int* __restrict__ batch) {
    int idx = blockIdx.x * blockDim.x + threadIdx.x;
    const int total = N_ATOMS * H4;
    if (idx >= total) return;
    int i = idx / H4;
    int c4 = idx - i * H4;
    int b = __ldg(&batch[i]);
    if (c4 == 0) atomicAdd(&g_cnt[b], 1.0f);
    const float4 v = *(const float4*)(g_h + (size_t)i * H + c4 * 4);
    float* dst = g_pooled + (size_t)b * H + c4 * 4;
    asm volatile("red.global.v4.f32.add [%0], {%1,%2,%3,%4};"
                 :: "l"(dst), "f"(v.x), "f"(v.y), "f"(v.z), "f"(v.w) : "memory");
}
__global__ void pool_divsplit_kernel() {
    int idx = blockIdx.x * blockDim.x + threadIdx.x;
    if (idx >= N_BATCH * H) return;
    int b = idx / H, c = idx - b * H;
    float v = g_pooled[idx] / fmaxf(g_cnt[b], 1.0f);
    __nv_bfloat16 hi, lo; split2(v, hi, lo);
    size_t base = (size_t)b * KP;
    g_pooled_s[base + c]         = hi;
    g_pooled_s[base + H + c]     = lo;
    g_pooled_s[base + 2 * H + c] = hi;
}

// ---------------- HMMA GEMM body (GBK=64, 2-stage, single-barrier) ----------
constexpr int GBM = 128, GBN = 128, GBK = 64;
constexpr int APAD = 8, BPAD = 8;
constexpr int AST = GBK + APAD;                 // 72
constexpr int BST = GBN + BPAD;                 // 136
constexpr uint32_t A_BYTES = GBM * AST * 2;     // 18432
constexpr uint32_t B_BYTES = GBK * BST * 2;     // 17408
constexpr uint32_t STG_BYTES = A_BYTES + B_BYTES;
constexpr int NSTAGE = 2;
constexpr uint32_t SMEM_SZ = NSTAGE * STG_BYTES;  // 71680

#define MMA16816(ac, A0, A1, A2, A3, B0, B1)                              \
    asm volatile(                                                         \
        "mma.sync.aligned.m16n8k16.row.col.f32.bf16.bf16.f32 "            \
        "{%0,%1,%2,%3},{%4,%5,%6,%7},{%8,%9},{%0,%1,%2,%3};\n"            \
        : "+f"(ac[0]), "+f"(ac[1]), "+f"(ac[2]), "+f"(ac[3])              \
        : "r"(A0), "r"(A1), "r"(A2), "r"(A3), "r"(B0), "r"(B1))

// EPI: 0 = +bias, 1 = ssp(+bias), 2 = (+bias)*g_Ct[m], 3 = +bias + g_h[m,n]
template <int ABUF, int BBUF, int CF32, int CSPL, int EPI, int M_, int KPA_>
__device__ __forceinline__
void gemm_body(const float* __restrict__ bias, float* out_param,
               size_t aoff, size_t boff, size_t csoff, int by) {
    const __nv_bfloat16* __restrict__ A  = bbuf<ABUF>() + aoff;
    const __nv_bfloat16* __restrict__ Bw = bbuf<BBUF>() + boff;
    float* Cf = nullptr;
    if constexpr (CF32 != B_NONE) Cf = fbuf<CF32>(out_param);
    __nv_bfloat16* Cs = nullptr;
    if constexpr (CSPL != B_NONE) Cs = bbuf<CSPL>() + csoff;

    extern __shared__ char dsm[];
    uint32_t sb;
    asm("{ .reg .u64 t; cvta.to.shared.u64 t, %1; cvt.u32.u64 %0, t; }"
        : "=r"(sb) : "l"(dsm));

    const int tid = threadIdx.x;
    const int lane = tid & 31, wid = tid >> 5;
    const int wm = (wid >> 1) * 32;
    const int wn = (wid & 1) * 64;
    const int bm = by * GBM, bn = blockIdx.x * GBN;

    float acc[2][8][4];
    #pragma unroll
    for (int mi = 0; mi < 2; mi++)
        #pragma unroll
        for (int ni = 0; ni < 8; ni++)
            #pragma unroll
            for (int c = 0; c < 4; c++) acc[mi][ni][c] = 0.0f;

    constexpr int KT = KPA_ / GBK;

    auto load_tiles = [&](int kt, int st) {
        int k0 = kt * GBK;
        uint32_t abase = sb + st * STG_BYTES;
        uint32_t bbase = abase + A_BYTES;
        // A: 128 rows x 64 cols bf16 = 1024 x 16B chunks
        #pragma unroll
        for (int c0 = 0; c0 < 4; c0++) {
            int c = tid + c0 * 256;
            int m = c >> 3, kc = (c & 7) * 8;
            const __nv_bfloat16* src = A + (size_t)(bm + m) * KPA_ + k0 + kc;
            uint32_t dst = abase + (m * AST + kc) * 2;
            int sz = (bm + m < M_) ? 16 : 0;
            asm volatile("cp.async.cg.shared.global [%0],[%1],16,%2;\n"
                         :: "r"(dst), "l"(src), "r"(sz));
        }
        // B: 64 rows x 128 cols bf16 = 1024 x 16B chunks
        #pragma unroll
        for (int c0 = 0; c0 < 4; c0++) {
            int c = tid + c0 * 256;
            int k = c >> 4, nc = (c & 15) * 8;
            const __nv_bfloat16* src = Bw + (size_t)(k0 + k) * H + bn + nc;
            uint32_t dst = bbase + (k * BST + nc) * 2;
            int sz = (bn + nc < H) ? 16 : 0;
            asm volatile("cp.async.cg.shared.global [%0],[%1],16,%2;\n"
                         :: "r"(dst), "l"(src), "r"(sz));
        }
        asm volatile("cp.async.commit_group;\n");
    };

    // prologue: preload 1 stage
    load_tiles(0, 0);

    #pragma unroll 1
    for (int kt = 0; kt < KT; kt++) {
        asm volatile("cp.async.wait_group 0;\n");
        __syncthreads();
        // refill the stage freed at iteration kt-1 with data for kt+1
        if (kt + 1 < KT) load_tiles(kt + 1, (kt + 1) & 1);

        int st = kt & 1;
        uint32_t abase = sb + st * STG_BYTES;
        uint32_t bbase = abase + A_BYTES;

        #pragma unroll
        for (int ks = 0; ks < 4; ks++) {
            const int kk = ks * 16;
            uint32_t a[2][4], b[4][4];
            #pragma unroll
            for (int mi = 0; mi < 2; mi++) {
                int row = wm + mi * 16 + (lane & 15);
                int col = kk + (lane >> 4) * 8;
                uint32_t addr = abase + (row * AST + col) * 2;
                asm volatile("ldmatrix.sync.aligned.m8n8.x4.shared.b16 {%0,%1,%2,%3},[%4];\n"
                             : "=r"(a[mi][0]), "=r"(a[mi][1]), "=r"(a[mi][2]), "=r"(a[mi][3])
                             : "r"(addr));
            }
            #pragma unroll
            for (int ng = 0; ng < 4; ng++) {
                int row = kk + (lane & 15);
                int col = wn + ng * 16 + (lane >> 4) * 8;
                uint32_t addr = bbase + (row * BST + col) * 2;
                asm volatile("ldmatrix.sync.aligned.m8n8.x4.trans.shared.b16 {%0,%1,%2,%3},[%4];\n"
                             : "=r"(b[ng][0]), "=r"(b[ng][1]), "=r"(b[ng][2]), "=r"(b[ng][3])
                             : "r"(addr));
            }
            #pragma unroll
            for (int mi = 0; mi < 2; mi++)
                #pragma unroll
                for (int ni = 0; ni < 8; ni++) {
                    uint32_t b0 = b[ni >> 1][(ni & 1) * 2 + 0];
                    uint32_t b1 = b[ni >> 1][(ni & 1) * 2 + 1];
                    MMA16816(acc[mi][ni], a[mi][0], a[mi][1], a[mi][2], a[mi][3], b0, b1);
                }
        }
        // no trailing barrier: next iteration's barrier protects stage reuse
    }

    // epilogue: paired (even, odd) column stores
    #pragma unroll
    for (int mi = 0; mi < 2; mi++) {
        #pragma unroll
        for (int r = 0; r < 2; r++) {
            int gm = bm + wm + mi * 16 + (lane >> 2) + r * 8;
            if (gm >= M_) continue;
            float cs = 0.0f;
            if constexpr (EPI == 2) cs = g_Ct[gm];
            #pragma unroll
            for (int ni = 0; ni < 8; ni++) {
                int gn = bn + wn + ni * 8 + (lane & 3) * 2;
                if (gn >= H) continue;          // pairs are even-aligned, H even
                float v0 = acc[mi][ni][r * 2 + 0];
                float v1 = acc[mi][ni][r * 2 + 1];
                if (bias) { v0 += bias[gn]; v1 += bias[gn + 1]; }
                if constexpr (EPI == 1) { v0 = sspf(v0); v1 = sspf(v1); }
                if constexpr (EPI == 2) { v0 *= cs; v1 *= cs; }
                if constexpr (EPI == 3) {
                    v0 += g_h[(size_t)gm * H + gn];
                    v1 += g_h[(size_t)gm * H + gn + 1];
                }
                if constexpr (CF32 != B_NONE)
                    *(float2*)(Cf + (size_t)gm * H + gn) = make_float2(v0, v1);
                if constexpr (CSPL != B_NONE) {
                    __nv_bfloat16 h0, l0, h1, l1;
                    split2(v0, h0, l0); split2(v1, h1, l1);
                    __nv_bfloat162 hp = {h0, h1}, lp = {l0, l1};
                    size_t base = (size_t)gm * KP;
                    *(__nv_bfloat162*)(Cs + base + gn)         = hp;
                    *(__nv_bfloat162*)(Cs + base + H + gn)     = lp;
                    *(__nv_bfloat162*)(Cs + base + 2 * H + gn) = hp;
                }
            }
        }
    }
}

// single-problem GEMM
template <int ABUF, int BBUF, int CF32, int CSPL, int EPI, int M_, int KPA_>
__global__ __launch_bounds__(256, 2)
void hgemm_kernel(const float* __restrict__ bias, float* out_param,
                  size_t aoff, size_t boff, size_t csoff) {
    gemm_body<ABUF, BBUF, CF32, CSPL, EPI, M_, KPA_>(
        bias, out_param, aoff, boff, csoff, blockIdx.y);
}

// fused launch: [ Y(k) | Wtab(k) | T1tab(k+1) ]
constexpr int NBY_Y = (N_ATOMS + GBM - 1) / GBM;   // 79
constexpr int NBY_T = S_TAB / GBM;                 // 8
__global__ __launch_bounds__(256, 2)
void hgemm_fused3(const float* __restrict__ b2, const float* __restrict__ b1n,
                  size_t offL1, size_t offW2, size_t offW1n,
                  size_t t1rd, size_t t1wr) {
    int by = blockIdx.y;
    if (by < NBY_Y) {
        gemm_body<B_HS, B_L1WS, B_Y, B_NONE, 0, N_ATOMS, KP>(
            nullptr, nullptr, 0, offL1, 0, by);
    } else if (by < NBY_Y + NBY_T) {
        gemm_body<B_T1S, B_W2S, B_WTAB, B_NONE, 2, S_TAB, KP>(
            b2, nullptr, t1rd, offW2, 0, by - NBY_Y);
    } else {
        gemm_body<B_RBFS, B_W1S, B_NONE, B_T1S, 1, S_TAB, KPG>(
            b1n, nullptr, 0, offW1n, t1wr, by - NBY_Y - NBY_T);
    }
}

// ---------------- CFConv gather: CSR, lerp, fused split output ----------------
__global__ void gather_kernel() {
    int idx = blockIdx.x * blockDim.x + threadIdx.x;
    const int total = N_ATOMS * H4;
    if (idx >= total) return;
    int i = idx / H4;
    int c4 = idx - i * H4;
    int k = c4 * 4;
    int beg = __ldg(&g_deg[i]);
    int end = __ldg(&g_deg[i + 1]);
    float4 acc = make_float4(0.f, 0.f, 0.f, 0.f);
    for (int j = beg; j < end; j++) {
        int s  = __ldg(&g_esrc[j]);
        int i0 = __ldg(&g_ei0s[j]);
        float f = __ldg(&g_efs[j]);
        const float4 y  = *(const float4*)(g_Y    + (size_t)s * H        + k);
        const float4 w0 = *(const float4*)(g_Wtab + (size_t)i0 * H       + k);
        const float4 w1 = *(const float4*)(g_Wtab + (size_t)(i0 + 1) * H + k);
        acc.x = fmaf(y.x, fmaf(f, w1.x - w0.x, w0.x), acc.x);
        acc.y = fmaf(y.y, fmaf(f, w1.y - w0.y, w0.y), acc.y);
        acc.z = fmaf(y.z, fmaf(f, w1.z - w0.z, w0.z), acc.z);
        acc.w = fmaf(y.w, fmaf(f, w1.w - w0.w, w0.w), acc.w);
    }
    split_store4(g_aggs, (size_t)i * KP, k, acc);
}

// ---------------- host side ----------------
extern "C" void kernel_launch(void* const* d_in, const int* in_sizes, int n_in,
                              void* d_out, int out_size) {
    const int*   z         = (const int*)  d_in[0];
    const float* pos       = (const float*)d_in[1];
    const int*   batch     = (const int*)  d_in[2];
    const int*   ei        = (const int*)  d_in[3];
    const float* emb       = (const float*)d_in[4];
    const float* mlp_w1    = (const float*)d_in[5];
    const float* mlp_b1    = (const float*)d_in[6];
    const float* mlp_w2    = (const float*)d_in[7];
    const float* mlp_b2    = (const float*)d_in[8];
    const float* lin1_w    = (const float*)d_in[9];
    const float* lin2_w    = (const float*)d_in[10];
    const float* lin2_b    = (const float*)d_in[11];
    const float* int_lin_w = (const float*)d_in[12];
    const float* int_lin_b = (const float*)d_in[13];
    const float* pool_w    = (const float*)d_in[14];
    const float* pool_b    = (const float*)d_in[15];
    float* out = (float*)d_out;

    cudaFuncSetAttribute(hgemm_kernel<B_RBFS, B_W1S, B_NONE, B_T1S, 1, S_TAB, KPG>,
                         cudaFuncAttributeMaxDynamicSharedMemorySize, (int)SMEM_SZ);
    cudaFuncSetAttribute(hgemm_fused3,
                         cudaFuncAttributeMaxDynamicSharedMemorySize, (int)SMEM_SZ);
    cudaFuncSetAttribute(hgemm_kernel<B_AGGS, B_L2WS, B_NONE, B_X1S, 1, N_ATOMS, KP>,
                         cudaFuncAttributeMaxDynamicSharedMemorySize, (int)SMEM_SZ);
    cudaFuncSetAttribute(hgemm_kernel<B_X1S, B_ILWS, B_H, B_HS, 3, N_ATOMS, KP>,
                         cudaFuncAttributeMaxDynamicSharedMemorySize, (int)SMEM_SZ);
    cudaFuncSetAttribute(hgemm_kernel<B_POOLS, B_PWS, B_PARAM, B_NONE, 0, N_BATCH, KP>,
                         cudaFuncAttributeMaxDynamicSharedMemorySize, (int)SMEM_SZ);

    // CSR build: zero -> histogram -> scan -> geometry+reorder
    zero_deg_kernel<<<(N_ATOMS + 1 + 255) / 256, 256>>>();
    hist_kernel<<<(N_EDGES + 255) / 256, 256>>>(ei);
    scan_kernel<<<1, 1024>>>();
    edge_reorder_kernel<<<(N_EDGES + 255) / 256, 256>>>(pos, ei);

    rbf_table_kernel<<<(S_TAB + 255) / 256, 256>>>();
    embed_kernel<<<(N_ATOMS * H4 + 255) / 256, 256>>>(z, emb);
    zero_pool_kernel<<<(N_BATCH * H4 + 255) / 256, 256>>>();
    {
        long long tot = (long long)L * 4 * H * H;
        split_w_all_kernel<<<(unsigned)((tot + 255) / 256), 256>>>(
            mlp_w2, lin1_w, lin2_w, int_lin_w);
        int tot2 = L * G * H + H * H;
        split_w1_pool_kernel<<<(tot2 + 255) / 256, 256>>>(mlp_w1, pool_w);
    }
    // prologue: T1tab(0) into ping-pong slot 0
    hgemm_kernel<B_RBFS, B_W1S, B_NONE, B_T1S, 1, S_TAB, KPG>
        <<<dim3(5, NBY_T), 256, SMEM_SZ>>>(mlp_b1, nullptr, 0, 0, 0);

    const dim3 gridN(5, NBY_Y);
    const dim3 gridB(5, 1);
    const int GA_BLK = (N_ATOMS * H4 + 255) / 256;
    const size_t T1SZ = (size_t)S_TAB * KP;

    for (int k = 0; k < L; k++) {
        const float* b2  = mlp_b2    + (size_t)k * H;
        const float* l2b = lin2_b    + (size_t)k * H;
        const float* ilb = int_lin_b + (size_t)k * H;
        const size_t oh  = (size_t)k * KP * H;
        const bool hasNext = (k + 1 < L);
        const float* b1n = hasNext ? (mlp_b1 + (size_t)(k + 1) * H) : nullptr;
        const size_t o1n = hasNext ? (size_t)(k + 1) * KPG * H : 0;
        const size_t t1rd = (size_t)(k & 1) * T1SZ;
        const size_t t1wr = (size_t)((k + 1) & 1) * T1SZ;

        // fused: Y(k) | Wtab(k) | T1tab(k+1)
        int gy = NBY_Y + NBY_T + (hasNext ? NBY_T : 0);
        hgemm_fused3<<<dim3(5, gy), 256, SMEM_SZ>>>(
            b2, b1n, oh, oh, o1n, t1rd, t1wr);
        // aggs = split( gather_csr(Y[src] * lerp(Wtab, d_e)) )
        gather_kernel<<<GA_BLK, 256>>>();
        // x1s = split(ssp(agg @ lin2_w + lin2_b))
        hgemm_kernel<B_AGGS, B_L2WS, B_NONE, B_X1S, 1, N_ATOMS, KP>
            <<<gridN, 256, SMEM_SZ>>>(l2b, nullptr, 0, oh, 0);
        // h = h + (x1 @ int_lin_w + int_lin_b); also refresh hs
        hgemm_kernel<B_X1S, B_ILWS, B_H, B_HS, 3, N_ATOMS, KP>
            <<<gridN, 256, SMEM_SZ>>>(ilb, nullptr, 0, oh, 0);
    }

    pool_sum_kernel<<<(N_ATOMS * H4 + 255) / 256, 256>>>(batch);
    pool_divsplit_kernel<<<(N_BATCH * H + 255) / 256, 256>>>();
    hgemm_kernel<B_POOLS, B_PWS, B_PARAM, B_NONE, 0, N_BATCH, KP>
        <<<gridB, 256, SMEM_SZ>>>(pool_b, out, 0, 0, 0);
}